// round 1
// baseline (speedup 1.0000x reference)
#include <cuda_runtime.h>
#include <math.h>

// Problem constants
#define BB   8
#define LL   3072
#define SS   3072
#define DD   512
#define HH   8
#define INDN 96
#define BLD  (BB*LL*DD)   // 12582912
#define PI_F 3.14159265358979323846f

// ---------------------------------------------------------------------------
// Scratch (device globals; allocation-free per harness rules)
// ---------------------------------------------------------------------------
__device__ float g_K0   [(size_t)BB*SS*DD];        // 50.3 MB
__device__ float g_V0   [(size_t)BB*SS*DD];        // 50.3 MB
__device__ float g_Q0   [(size_t)INDN*DD];
__device__ float g_kom0 [(size_t)BB*SS*16];
__device__ float g_kth0 [(size_t)BB*SS*16];
__device__ float g_qom0 [(size_t)INDN*16];
__device__ float g_qth0 [(size_t)INDN*16];
__device__ float g_Qr0  [(size_t)INDN*HH*128];
__device__ float g_Kr0  [(size_t)BB*SS*HH*128];    // 100.7 MB
__device__ float g_scores[(size_t)BB*HH*INDN*SS];  // 75.5 MB (reused by layer 1)
__device__ float g_attn0[(size_t)BB*INDN*DD];
__device__ float g_indB [(size_t)BB*INDN*DD];
__device__ float g_indC [(size_t)BB*INDN*DD];
__device__ float g_Q1   [(size_t)BB*LL*DD];        // 50.3 MB
__device__ float g_K1   [(size_t)BB*INDN*DD];
__device__ float g_V1   [(size_t)BB*INDN*DD];
__device__ float g_qom1 [(size_t)BB*LL*16];
__device__ float g_qth1 [(size_t)BB*LL*16];
__device__ float g_kom1 [(size_t)BB*INDN*16];
__device__ float g_kth1 [(size_t)BB*INDN*16];
__device__ float g_Qr1  [(size_t)BB*LL*HH*128];    // 100.7 MB
__device__ float g_Kr1  [(size_t)BB*INDN*HH*128];
__device__ float g_attn1[(size_t)BB*LL*DD];        // 50.3 MB
__device__ float g_pen[2];

// ---------------------------------------------------------------------------
// GEMM (NN): C[N,P] = A[N,512] @ W[512,P] + bias.  128x128x8, 8x8/thread.
// ---------------------------------------------------------------------------
__global__ __launch_bounds__(256) void gemm_nn(
    const float* __restrict__ A, const float* __restrict__ W,
    const float* __restrict__ bias, float* __restrict__ C, int N, int P)
{
    __shared__ float As[8][128];
    __shared__ float Bs[8][132];
    int tid = threadIdx.x;
    int rowBase = blockIdx.y * 128;
    int colBase = blockIdx.x * 128;
    int ty = tid >> 4, tx = tid & 15;
    float acc[8][8];
#pragma unroll
    for (int i = 0; i < 8; i++)
#pragma unroll
        for (int j = 0; j < 8; j++) acc[i][j] = 0.f;

    int aRow = tid >> 1;
    int aK   = (tid & 1) * 4;
    int wK   = tid >> 5;
    int wCol = (tid & 31) * 4;
    bool aValid = (rowBase + aRow) < N;
    const float* Aptr = A + (size_t)(rowBase + aRow) * 512 + aK;
    const float* Wptr = W + (size_t)wK * P + colBase + wCol;

    for (int k0 = 0; k0 < 512; k0 += 8) {
        float4 av = aValid ? *(const float4*)(Aptr + k0)
                           : make_float4(0.f, 0.f, 0.f, 0.f);
        As[aK+0][aRow] = av.x; As[aK+1][aRow] = av.y;
        As[aK+2][aRow] = av.z; As[aK+3][aRow] = av.w;
        float4 wv = *(const float4*)(Wptr + (size_t)k0 * P);
        Bs[wK][wCol+0] = wv.x; Bs[wK][wCol+1] = wv.y;
        Bs[wK][wCol+2] = wv.z; Bs[wK][wCol+3] = wv.w;
        __syncthreads();
#pragma unroll
        for (int k = 0; k < 8; k++) {
            float ar[8], br[8];
#pragma unroll
            for (int i = 0; i < 8; i++) ar[i] = As[k][i*16 + ty];
#pragma unroll
            for (int j = 0; j < 8; j++) br[j] = Bs[k][j*16 + tx];
#pragma unroll
            for (int i = 0; i < 8; i++)
#pragma unroll
                for (int j = 0; j < 8; j++)
                    acc[i][j] = fmaf(ar[i], br[j], acc[i][j]);
        }
        __syncthreads();
    }
#pragma unroll
    for (int i = 0; i < 8; i++) {
        int row = rowBase + i*16 + ty;
        if (row >= N) continue;
#pragma unroll
        for (int j = 0; j < 8; j++) {
            int col = colBase + j*16 + tx;
            C[(size_t)row * P + col] = acc[i][j] + bias[col];
        }
    }
}

// ---------------------------------------------------------------------------
// Small GEMM: C[N,16] = act(A[N,512] @ W[512,16] + bias). act: 0 none, 1 relu,
// 2 tanh*pi.
// ---------------------------------------------------------------------------
__global__ __launch_bounds__(256) void gemm_small(
    const float* __restrict__ A, const float* __restrict__ W,
    const float* __restrict__ bias, float* __restrict__ C, int N, int act)
{
    int tid = threadIdx.x;
    int r = blockIdx.x * 16 + (tid >> 4);
    int c = tid & 15;
    if (r >= N) return;
    const float* a = A + (size_t)r * 512;
    float acc = 0.f;
#pragma unroll 8
    for (int k = 0; k < 512; k++)
        acc = fmaf(__ldg(a + k), __ldg(W + k*16 + c), acc);
    acc += bias[c];
    if (act == 1)      acc = fmaxf(acc, 0.f);
    else if (act == 2) acc = tanhf(acc) * PI_F;
    C[(size_t)r * 16 + c] = acc;
}

// ---------------------------------------------------------------------------
// Rotation builders.  Qr/Kr layout: [row, h, m*64 + block*16 + i]
// ---------------------------------------------------------------------------
__global__ void build_qr(const float* __restrict__ Q, const float* __restrict__ om,
                         const float* __restrict__ th, float* __restrict__ Qr,
                         int seq, float invSeq)
{
    int row = blockIdx.x;
    int tid = threadIdx.x;
    int h = tid >> 5, m = (tid >> 4) & 1, i = tid & 15;
    float pos = (float)(row % seq) * invSeq;
    int oi = row * 16 + h * 2 + m;
    float ang = fmaf(om[oi], pos, th[oi]);
    float sn, cs; sincosf(ang, &sn, &cs);
    const float* q = Q + (size_t)row * 512 + h * 64;
    float q0 = q[i], q1 = q[16+i], q2 = q[32+i], q3 = q[48+i];
    float* o = Qr + ((size_t)row * HH + h) * 128 + m * 64;
    o[i]      = q0*cs - q1*sn;
    o[16 + i] = q1*cs + q0*sn;
    o[32 + i] = q2*cs + q3*sn;
    o[48 + i] = q3*cs - q2*sn;
}

__global__ void build_kr(const float* __restrict__ K, const float* __restrict__ om,
                         const float* __restrict__ th, float* __restrict__ Kr,
                         int seq, float invSeq)
{
    int row = blockIdx.x;
    int tid = threadIdx.x;
    int h = tid >> 5, m = (tid >> 4) & 1, i = tid & 15;
    float pos = (float)(row % seq) * invSeq;
    int oi = row * 16 + h * 2 + m;
    float ang = fmaf(om[oi], pos, th[oi]);
    float sn, cs; sincosf(ang, &sn, &cs);
    const float* k = K + (size_t)row * 512 + h * 64;
    float k0 = k[i], k1 = k[16+i], k2 = k[32+i], k3 = k[48+i];
    float* o = Kr + ((size_t)row * HH + h) * 128 + m * 64;
    o[i]      = k0*cs - k2*sn;
    o[16 + i] = k1*cs - k3*sn;
    o[32 + i] = k2*cs + k0*sn;
    o[48 + i] = k3*cs + k1*sn;
}

// ---------------------------------------------------------------------------
// Scores (NT GEMM per (b,h)): scores[bh, l, s] = (1/16) * Qr[l,:] . Kr[s,:]
// 64x64x16 tiles, 4x4/thread.  qBstride = row-batch-stride of Qr (0 => shared).
// ---------------------------------------------------------------------------
__global__ __launch_bounds__(256) void gemm_nt(
    const float* __restrict__ Qr, size_t qBstride,
    const float* __restrict__ Kr, float* __restrict__ scores, int Lq, int S)
{
    __shared__ float As[16][68];
    __shared__ float Bs[16][68];
    int tid = threadIdx.x;
    int bh = blockIdx.z, b = bh >> 3, h = bh & 7;
    const float* Ab = Qr + (size_t)b * qBstride + (size_t)h * 128;
    const float* Bb = Kr + ((size_t)b * S * HH + h) * 128;
    float* C = scores + (size_t)bh * Lq * S;
    int lBase = blockIdx.y * 64, sBase = blockIdx.x * 64;
    int ty = tid >> 4, tx = tid & 15;
    float acc[4][4];
#pragma unroll
    for (int i = 0; i < 4; i++)
#pragma unroll
        for (int j = 0; j < 4; j++) acc[i][j] = 0.f;
    int lr = tid >> 2, lk = (tid & 3) * 4;

    for (int k0 = 0; k0 < 128; k0 += 16) {
        int r = lBase + lr;
        float4 av = (r < Lq) ? *(const float4*)(Ab + (size_t)r*1024 + k0 + lk)
                             : make_float4(0.f,0.f,0.f,0.f);
        As[lk+0][lr] = av.x; As[lk+1][lr] = av.y;
        As[lk+2][lr] = av.z; As[lk+3][lr] = av.w;
        int sr = sBase + lr;
        float4 bv = (sr < S) ? *(const float4*)(Bb + (size_t)sr*1024 + k0 + lk)
                             : make_float4(0.f,0.f,0.f,0.f);
        Bs[lk+0][lr] = bv.x; Bs[lk+1][lr] = bv.y;
        Bs[lk+2][lr] = bv.z; Bs[lk+3][lr] = bv.w;
        __syncthreads();
#pragma unroll
        for (int k = 0; k < 16; k++) {
            float ar[4], br[4];
#pragma unroll
            for (int i = 0; i < 4; i++) ar[i] = As[k][i*16 + ty];
#pragma unroll
            for (int j = 0; j < 4; j++) br[j] = Bs[k][j*16 + tx];
#pragma unroll
            for (int i = 0; i < 4; i++)
#pragma unroll
                for (int j = 0; j < 4; j++)
                    acc[i][j] = fmaf(ar[i], br[j], acc[i][j]);
        }
        __syncthreads();
    }
#pragma unroll
    for (int i = 0; i < 4; i++) {
        int l = lBase + i*16 + ty;
        if (l >= Lq) continue;
#pragma unroll
        for (int j = 0; j < 4; j++) {
            int s = sBase + j*16 + tx;
            if (s < S) C[(size_t)l * S + s] = acc[i][j] * 0.0625f;
        }
    }
}

// ---------------------------------------------------------------------------
// Softmax over s + weighted sum of V.  One block per (b,h,l).
// out[b,l,h*64+e] = sum_s softmax(scores)[s] * V[b,s,h*64+e]
// ---------------------------------------------------------------------------
__global__ __launch_bounds__(256) void softmax_av(
    const float* __restrict__ scores, const float* __restrict__ V,
    float* __restrict__ out, int Lq, int S)
{
    __shared__ float p[3072];
    __shared__ float red[256];
    int l = blockIdx.x, h = blockIdx.y, b = blockIdx.z;
    int tid = threadIdx.x;
    const float* srow = scores + (((size_t)(b*HH + h) * Lq) + l) * S;

    float lmax = -3.4e38f;
    for (int s = tid; s < S; s += 256) { float v = srow[s]; p[s] = v; lmax = fmaxf(lmax, v); }
    red[tid] = lmax; __syncthreads();
    for (int off = 128; off > 0; off >>= 1) {
        if (tid < off) red[tid] = fmaxf(red[tid], red[tid + off]);
        __syncthreads();
    }
    float mx = red[0]; __syncthreads();

    float lsum = 0.f;
    for (int s = tid; s < S; s += 256) { float e = __expf(p[s] - mx); p[s] = e; lsum += e; }
    red[tid] = lsum; __syncthreads();
    for (int off = 128; off > 0; off >>= 1) {
        if (tid < off) red[tid] += red[tid + off];
        __syncthreads();
    }
    float inv = 1.f / red[0]; __syncthreads();

    int e = tid & 63, gq = tid >> 6;
    float acc = 0.f;
    for (int s = gq; s < S; s += 4)
        acc = fmaf(p[s], V[(((size_t)b*S + s) << 9) + (h << 6) + e], acc);
    red[tid] = acc; __syncthreads();
    if (gq == 0) {
        float r = (red[e] + red[64+e] + red[128+e] + red[192+e]) * inv;
        out[(((size_t)b*Lq + l) << 9) + (h << 6) + e] = r;
    }
}

// ---------------------------------------------------------------------------
// Trend norm: series_decomp(25) + LayerNorm(seasonal) + trend
// ---------------------------------------------------------------------------
__global__ __launch_bounds__(256) void trend_norm(
    const float* __restrict__ x, const float* __restrict__ gm,
    const float* __restrict__ bt, float* __restrict__ y)
{
    __shared__ float seas[512];
    __shared__ float trend[512];
    __shared__ float red[256];
    int b = blockIdx.y, t = blockIdx.x, tid = threadIdx.x;
    const float* xb = x + (size_t)b * INDN * 512;
    float ls = 0.f, ls2 = 0.f;
    for (int d = tid; d < 512; d += 256) {
        float tr = 0.f;
#pragma unroll
        for (int j = -12; j <= 12; j++) {
            int tt = t + j;
            tt = tt < 0 ? 0 : (tt > INDN-1 ? INDN-1 : tt);
            tr += xb[(size_t)tt * 512 + d];
        }
        tr *= (1.0f / 25.0f);
        float sv = xb[(size_t)t * 512 + d] - tr;
        seas[d] = sv; trend[d] = tr;
        ls += sv; ls2 += sv * sv;
    }
    red[tid] = ls; __syncthreads();
    for (int off = 128; off > 0; off >>= 1) { if (tid < off) red[tid] += red[tid+off]; __syncthreads(); }
    float mu = red[0] * (1.f/512.f); __syncthreads();
    red[tid] = ls2; __syncthreads();
    for (int off = 128; off > 0; off >>= 1) { if (tid < off) red[tid] += red[tid+off]; __syncthreads(); }
    float var = red[0] * (1.f/512.f) - mu*mu;
    float rs = rsqrtf(var + 1e-5f);
    for (int d = tid; d < 512; d += 256)
        y[((size_t)b*INDN + t) * 512 + d] = (seas[d] - mu) * rs * gm[d] + bt[d] + trend[d];
}

// ---------------------------------------------------------------------------
// Penalties: om first-difference^2 along sequence, th^2; scaled accumulation.
// ---------------------------------------------------------------------------
__global__ void zero_pen() { g_pen[0] = 0.f; g_pen[1] = 0.f; }

__global__ __launch_bounds__(256) void penalty_kernel(
    const float* __restrict__ om, const float* __restrict__ th,
    int total, int seq, float scale)
{
    float omp = 0.f, thp = 0.f;
    for (int idx = blockIdx.x * 256 + threadIdx.x; idx < total; idx += gridDim.x * 256) {
        int n = idx >> 4;
        int sIn = n % seq;
        float t = th[idx]; thp += t * t;
        if (sIn < seq - 1) { float d = om[idx + 16] - om[idx]; omp += d * d; }
    }
#pragma unroll
    for (int o = 16; o > 0; o >>= 1) {
        omp += __shfl_down_sync(0xffffffffu, omp, o);
        thp += __shfl_down_sync(0xffffffffu, thp, o);
    }
    __shared__ float sho[8], sht[8];
    int wid = threadIdx.x >> 5, lid = threadIdx.x & 31;
    if (lid == 0) { sho[wid] = omp; sht[wid] = thp; }
    __syncthreads();
    if (threadIdx.x == 0) {
        float so = 0.f, st = 0.f;
        for (int w = 0; w < 8; w++) { so += sho[w]; st += sht[w]; }
        atomicAdd(&g_pen[0], so * scale);
        atomicAdd(&g_pen[1], st * scale);
    }
}

__global__ void finalize_kernel(float* out, int out_size)
{
    if (out_size >= BLD + 2) {
        out[BLD]     = g_pen[0];
        out[BLD + 1] = g_pen[1];
    }
}

// ---------------------------------------------------------------------------
// Host launcher
// ---------------------------------------------------------------------------
#define SYMADDR(p, s) do { void* _t = nullptr; cudaGetSymbolAddress(&_t, s); (p) = (float*)_t; } while (0)

extern "C" void kernel_launch(void* const* d_in, const int* in_sizes, int n_in,
                              void* d_out, int out_size)
{
    (void)in_sizes; (void)n_in;
    const float* queries = (const float*)d_in[0];
    const float* keys    = (const float*)d_in[1];
    const float* values  = (const float*)d_in[2];
    const float* Wq  = (const float*)d_in[3];
    const float* bq  = (const float*)d_in[4];
    const float* Wk  = (const float*)d_in[5];
    const float* bk  = (const float*)d_in[6];
    const float* Wv  = (const float*)d_in[7];
    const float* bv  = (const float*)d_in[8];
    const float* Wqo = (const float*)d_in[9];
    const float* bqo = (const float*)d_in[10];
    const float* Wko = (const float*)d_in[11];
    const float* bko = (const float*)d_in[12];
    const float* Wqt = (const float*)d_in[13];
    const float* bqt = (const float*)d_in[14];
    const float* Wkt = (const float*)d_in[15];
    const float* bkt = (const float*)d_in[16];
    const float* Wo  = (const float*)d_in[17];
    const float* bo  = (const float*)d_in[18];
    const float* Ibuf = (const float*)d_in[19];
    const float* ln_g = (const float*)d_in[20];
    const float* ln_b = (const float*)d_in[21];
    float* out = (float*)d_out;

    const int NBS = BB * SS;      // 24576
    const int NBI = BB * INDN;    // 768
    const int W2  = 512 * 512;    // slice stride of 512x512 weights
    const int W2S = 512 * 16;     // slice stride of 512x16 weights

    float *pK0, *pV0, *pQ0, *pkom0, *pkth0, *pqom0, *pqth0, *pQr0, *pKr0, *pScores;
    float *pAttn0, *pIndB, *pIndC, *pQ1, *pK1, *pV1, *pqom1, *pqth1, *pkom1, *pkth1;
    float *pQr1, *pKr1, *pAttn1;
    SYMADDR(pK0, g_K0);     SYMADDR(pV0, g_V0);     SYMADDR(pQ0, g_Q0);
    SYMADDR(pkom0, g_kom0); SYMADDR(pkth0, g_kth0);
    SYMADDR(pqom0, g_qom0); SYMADDR(pqth0, g_qth0);
    SYMADDR(pQr0, g_Qr0);   SYMADDR(pKr0, g_Kr0);   SYMADDR(pScores, g_scores);
    SYMADDR(pAttn0, g_attn0); SYMADDR(pIndB, g_indB); SYMADDR(pIndC, g_indC);
    SYMADDR(pQ1, g_Q1);     SYMADDR(pK1, g_K1);     SYMADDR(pV1, g_V1);
    SYMADDR(pqom1, g_qom1); SYMADDR(pqth1, g_qth1);
    SYMADDR(pkom1, g_kom1); SYMADDR(pkth1, g_kth1);
    SYMADDR(pQr1, g_Qr1);   SYMADDR(pKr1, g_Kr1);   SYMADDR(pAttn1, g_attn1);

    // ------------------------ Layer 0 (inducings x keys/values) -------------
    gemm_nn<<<dim3(4, 192), 256>>>(keys,   Wk, bk, pK0, NBS, 512);
    gemm_nn<<<dim3(4, 192), 256>>>(values, Wv, bv, pV0, NBS, 512);
    gemm_nn<<<dim3(4, 1),   256>>>(Ibuf,   Wq, bq, pQ0, INDN, 512);

    gemm_small<<<NBS/16, 256>>>(keys, Wko, bko, pkom0, NBS, 1);
    gemm_small<<<NBS/16, 256>>>(keys, Wkt, bkt, pkth0, NBS, 2);
    gemm_small<<<INDN/16, 256>>>(Ibuf, Wqo, bqo, pqom0, INDN, 1);
    gemm_small<<<INDN/16, 256>>>(Ibuf, Wqt, bqt, pqth0, INDN, 2);

    zero_pen<<<1, 1>>>();
    penalty_kernel<<<6, 256>>>(pqom0, pqth0, INDN*16, INDN, (float)BB);
    penalty_kernel<<<1024, 256>>>(pkom0, pkth0, NBS*16, SS, 1.f);

    build_qr<<<INDN, 256>>>(pQ0, pqom0, pqth0, pQr0, INDN, 1.f/INDN);
    build_kr<<<NBS,  256>>>(pK0, pkom0, pkth0, pKr0, SS,   1.f/SS);

    gemm_nt<<<dim3(SS/64, 2, BB*HH), 256>>>(pQr0, (size_t)0, pKr0, pScores, INDN, SS);
    softmax_av<<<dim3(INDN, HH, BB), 256>>>(pScores, pV0, pAttn0, INDN, SS);

    gemm_nn<<<dim3(4, 6), 256>>>(pAttn0, Wo, bo, pIndB, NBI, 512);
    trend_norm<<<dim3(INDN, BB), 256>>>(pIndB, ln_g, ln_b, pIndC);

    // ------------------------ Layer 1 (queries x inducings) -----------------
    gemm_nn<<<dim3(4, 192), 256>>>(queries, Wq + W2, bq + 512, pQ1, NBS, 512);
    gemm_nn<<<dim3(4, 6),   256>>>(pIndC,   Wk + W2, bk + 512, pK1, NBI, 512);
    gemm_nn<<<dim3(4, 6),   256>>>(pIndC,   Wv + W2, bv + 512, pV1, NBI, 512);

    gemm_small<<<NBS/16, 256>>>(queries, Wqo + W2S, bqo + 16, pqom1, NBS, 1);
    gemm_small<<<NBS/16, 256>>>(queries, Wqt + W2S, bqt + 16, pqth1, NBS, 2);
    gemm_small<<<NBI/16, 256>>>(pIndC,   Wko + W2S, bko + 16, pkom1, NBI, 1);
    gemm_small<<<NBI/16, 256>>>(pIndC,   Wkt + W2S, bkt + 16, pkth1, NBI, 2);

    penalty_kernel<<<1024, 256>>>(pqom1, pqth1, NBS*16, LL, 1.f);
    penalty_kernel<<<48, 256>>>(pkom1, pkth1, NBI*16, INDN, 1.f);

    build_qr<<<NBS, 256>>>(pQ1, pqom1, pqth1, pQr1, LL,   1.f/LL);
    build_kr<<<NBI, 256>>>(pK1, pkom1, pkth1, pKr1, INDN, 1.f/INDN);

    gemm_nt<<<dim3(2, LL/64, BB*HH), 256>>>(pQr1, (size_t)LL*HH*128, pKr1, pScores, LL, INDN);
    softmax_av<<<dim3(LL, HH, BB), 256>>>(pScores, pV1, pAttn1, LL, INDN);

    gemm_nn<<<dim3(4, 192), 256>>>(pAttn1, Wo + W2, bo + 512, out, NBS, 512);

    finalize_kernel<<<1, 1>>>(out, out_size);
}

// round 2
// speedup vs baseline: 1.5039x; 1.5039x over previous
#include <cuda_runtime.h>
#include <math.h>

// Problem constants
#define BB   8
#define LL   3072
#define SS   3072
#define DD   512
#define HH   8
#define INDN 96
#define BLD  (BB*LL*DD)   // 12582912
#define PI_F 3.14159265358979323846f

// ---------------------------------------------------------------------------
// Scratch (device globals; allocation-free per harness rules)
// ---------------------------------------------------------------------------
__device__ float g_K0   [(size_t)BB*SS*DD];
__device__ float g_V0   [(size_t)BB*SS*DD];
__device__ float g_Q0   [(size_t)INDN*DD];
__device__ float g_kom0 [(size_t)BB*SS*16];
__device__ float g_kth0 [(size_t)BB*SS*16];
__device__ float g_qom0 [(size_t)INDN*16];
__device__ float g_qth0 [(size_t)INDN*16];
__device__ float g_Qr0  [(size_t)INDN*HH*128];
__device__ float g_Kr0  [(size_t)BB*SS*HH*128];
__device__ float g_scores[(size_t)BB*HH*LL*SS > (size_t)BB*HH*INDN*SS ?
                          (size_t)BB*HH*LL*96 : (size_t)BB*HH*INDN*SS]; // max(L0, L1) score buf
__device__ float g_attn0[(size_t)BB*INDN*DD];
__device__ float g_indB [(size_t)BB*INDN*DD];
__device__ float g_indC [(size_t)BB*INDN*DD];
__device__ float g_Q1   [(size_t)BB*LL*DD];
__device__ float g_K1   [(size_t)BB*INDN*DD];
__device__ float g_V1   [(size_t)BB*INDN*DD];
__device__ float g_qom1 [(size_t)BB*LL*16];
__device__ float g_qth1 [(size_t)BB*LL*16];
__device__ float g_kom1 [(size_t)BB*INDN*16];
__device__ float g_kth1 [(size_t)BB*INDN*16];
__device__ float g_Qr1  [(size_t)BB*LL*HH*128];
__device__ float g_Kr1  [(size_t)BB*INDN*HH*128];
__device__ float g_attn1[(size_t)BB*LL*DD];
__device__ float g_pen[2];

// ---------------------------------------------------------------------------
// Packed f32x2 helpers (FFMA2 path — only reachable via PTX fma.rn.f32x2)
// ---------------------------------------------------------------------------
__device__ __forceinline__ unsigned long long pk2(float x, float y) {
    unsigned long long r;
    asm("mov.b64 %0, {%1, %2};" : "=l"(r) : "f"(x), "f"(y));
    return r;
}
__device__ __forceinline__ void fma2(unsigned long long& d,
                                     unsigned long long a, unsigned long long b) {
    asm("fma.rn.f32x2 %0, %1, %2, %0;" : "+l"(d) : "l"(a), "l"(b));
}
__device__ __forceinline__ float2 upk2(unsigned long long v) {
    float2 r;
    asm("mov.b64 {%0, %1}, %2;" : "=f"(r.x), "=f"(r.y) : "l"(v));
    return r;
}

// ---------------------------------------------------------------------------
// GEMM (NN): C[N,P] = A[N,512] @ W[512,P] + bias.  128x128x16 tile, 8x8/thread
// with adjacent row-pairs -> packed f32x2 accumulation.
// ---------------------------------------------------------------------------
__global__ __launch_bounds__(256, 2) void gemm_nn(
    const float* __restrict__ A, const float* __restrict__ W,
    const float* __restrict__ bias, float* __restrict__ C, int N, int P)
{
    __shared__ float As[16][132];
    __shared__ float Bs[16][132];
    int tid = threadIdx.x;
    int rowBase = blockIdx.y * 128;
    int colBase = blockIdx.x * 128;
    int ty = tid >> 4, tx = tid & 15;

    unsigned long long acc[4][8];
#pragma unroll
    for (int p = 0; p < 4; p++)
#pragma unroll
        for (int j = 0; j < 8; j++) acc[p][j] = 0ull;

    int aRow = tid >> 2;          // 0..63
    int aK   = (tid & 3) * 4;     // 0,4,8,12
    int bK   = tid >> 4;          // 0..15
    int bCol = (tid & 15) * 4;    // 0..60
    bool v0 = (rowBase + aRow) < N;
    bool v1 = (rowBase + aRow + 64) < N;
    const float* Ap0 = A + (size_t)(rowBase + aRow) * 512 + aK;
    const float* Ap1 = Ap0 + (size_t)64 * 512;
    const float* Wp  = W + (size_t)bK * P + colBase + bCol;

    for (int k0 = 0; k0 < 512; k0 += 16) {
        float4 a0 = v0 ? *(const float4*)(Ap0 + k0) : make_float4(0.f,0.f,0.f,0.f);
        float4 a1 = v1 ? *(const float4*)(Ap1 + k0) : make_float4(0.f,0.f,0.f,0.f);
        As[aK+0][aRow] = a0.x; As[aK+1][aRow] = a0.y;
        As[aK+2][aRow] = a0.z; As[aK+3][aRow] = a0.w;
        As[aK+0][aRow+64] = a1.x; As[aK+1][aRow+64] = a1.y;
        As[aK+2][aRow+64] = a1.z; As[aK+3][aRow+64] = a1.w;
        float4 b0 = *(const float4*)(Wp + (size_t)k0 * P);
        float4 b1 = *(const float4*)(Wp + (size_t)k0 * P + 64);
        *(float4*)&Bs[bK][bCol]      = b0;
        *(float4*)&Bs[bK][bCol + 64] = b1;
        __syncthreads();
#pragma unroll
        for (int k = 0; k < 16; k++) {
            float4 av0 = *(const float4*)&As[k][ty*4];
            float4 av1 = *(const float4*)&As[k][64 + ty*4];
            float4 bv0 = *(const float4*)&Bs[k][tx*4];
            float4 bv1 = *(const float4*)&Bs[k][64 + tx*4];
            unsigned long long ap[4];
            ap[0] = pk2(av0.x, av0.y); ap[1] = pk2(av0.z, av0.w);
            ap[2] = pk2(av1.x, av1.y); ap[3] = pk2(av1.z, av1.w);
            unsigned long long bd[8];
            bd[0] = pk2(bv0.x, bv0.x); bd[1] = pk2(bv0.y, bv0.y);
            bd[2] = pk2(bv0.z, bv0.z); bd[3] = pk2(bv0.w, bv0.w);
            bd[4] = pk2(bv1.x, bv1.x); bd[5] = pk2(bv1.y, bv1.y);
            bd[6] = pk2(bv1.z, bv1.z); bd[7] = pk2(bv1.w, bv1.w);
#pragma unroll
            for (int p = 0; p < 4; p++)
#pragma unroll
                for (int j = 0; j < 8; j++)
                    fma2(acc[p][j], ap[p], bd[j]);
        }
        __syncthreads();
    }

#pragma unroll
    for (int p = 0; p < 4; p++) {
        int row = rowBase + ((p < 2) ? (ty*4 + p*2) : (64 + ty*4 + (p-2)*2));
#pragma unroll
        for (int j = 0; j < 8; j++) {
            int col = colBase + ((j < 4) ? (tx*4 + j) : (64 + tx*4 + (j-4)));
            float2 r = upk2(acc[p][j]);
            float bb = bias[col];
            if (row < N)     C[(size_t)row * P + col]     = r.x + bb;
            if (row + 1 < N) C[(size_t)(row+1) * P + col] = r.y + bb;
        }
    }
}

// ---------------------------------------------------------------------------
// Scores (NT GEMM per (b,h)): scores[bh,l,s] = (1/16) Qr[l,:].Kr[s,:], K=128.
// 128x128 tile, same f32x2 structure.  qBstride=0 => Q shared across batch.
// ---------------------------------------------------------------------------
__global__ __launch_bounds__(256, 2) void gemm_nt(
    const float* __restrict__ Qr, size_t qBstride,
    const float* __restrict__ Kr, float* __restrict__ scores, int Lq, int S)
{
    __shared__ float As[16][132];
    __shared__ float Bs[16][132];
    int tid = threadIdx.x;
    int bh = blockIdx.z, b = bh >> 3, h = bh & 7;
    const float* Ab = Qr + (size_t)b * qBstride + (size_t)h * 128;
    const float* Bb = Kr + ((size_t)b * S * HH + h) * 128;
    float* C = scores + (size_t)bh * Lq * S;
    int lBase = blockIdx.y * 128, sBase = blockIdx.x * 128;
    int ty = tid >> 4, tx = tid & 15;

    unsigned long long acc[4][8];
#pragma unroll
    for (int p = 0; p < 4; p++)
#pragma unroll
        for (int j = 0; j < 8; j++) acc[p][j] = 0ull;

    int lr = tid >> 2;           // 0..63
    int lk = (tid & 3) * 4;      // 0,4,8,12

    for (int k0 = 0; k0 < 128; k0 += 16) {
        int r0 = lBase + lr, r1 = r0 + 64;
        float4 a0 = (r0 < Lq) ? *(const float4*)(Ab + (size_t)r0*1024 + k0 + lk)
                              : make_float4(0.f,0.f,0.f,0.f);
        float4 a1 = (r1 < Lq) ? *(const float4*)(Ab + (size_t)r1*1024 + k0 + lk)
                              : make_float4(0.f,0.f,0.f,0.f);
        As[lk+0][lr] = a0.x; As[lk+1][lr] = a0.y;
        As[lk+2][lr] = a0.z; As[lk+3][lr] = a0.w;
        As[lk+0][lr+64] = a1.x; As[lk+1][lr+64] = a1.y;
        As[lk+2][lr+64] = a1.z; As[lk+3][lr+64] = a1.w;
        int s0 = sBase + lr, s1 = s0 + 64;
        float4 b0v = (s0 < S) ? *(const float4*)(Bb + (size_t)s0*1024 + k0 + lk)
                              : make_float4(0.f,0.f,0.f,0.f);
        float4 b1v = (s1 < S) ? *(const float4*)(Bb + (size_t)s1*1024 + k0 + lk)
                              : make_float4(0.f,0.f,0.f,0.f);
        Bs[lk+0][lr] = b0v.x; Bs[lk+1][lr] = b0v.y;
        Bs[lk+2][lr] = b0v.z; Bs[lk+3][lr] = b0v.w;
        Bs[lk+0][lr+64] = b1v.x; Bs[lk+1][lr+64] = b1v.y;
        Bs[lk+2][lr+64] = b1v.z; Bs[lk+3][lr+64] = b1v.w;
        __syncthreads();
#pragma unroll
        for (int k = 0; k < 16; k++) {
            float4 av0 = *(const float4*)&As[k][ty*4];
            float4 av1 = *(const float4*)&As[k][64 + ty*4];
            float4 bv0 = *(const float4*)&Bs[k][tx*4];
            float4 bv1 = *(const float4*)&Bs[k][64 + tx*4];
            unsigned long long ap[4];
            ap[0] = pk2(av0.x, av0.y); ap[1] = pk2(av0.z, av0.w);
            ap[2] = pk2(av1.x, av1.y); ap[3] = pk2(av1.z, av1.w);
            unsigned long long bd[8];
            bd[0] = pk2(bv0.x, bv0.x); bd[1] = pk2(bv0.y, bv0.y);
            bd[2] = pk2(bv0.z, bv0.z); bd[3] = pk2(bv0.w, bv0.w);
            bd[4] = pk2(bv1.x, bv1.x); bd[5] = pk2(bv1.y, bv1.y);
            bd[6] = pk2(bv1.z, bv1.z); bd[7] = pk2(bv1.w, bv1.w);
#pragma unroll
            for (int p = 0; p < 4; p++)
#pragma unroll
                for (int j = 0; j < 8; j++)
                    fma2(acc[p][j], ap[p], bd[j]);
        }
        __syncthreads();
    }

#pragma unroll
    for (int p = 0; p < 4; p++) {
        int l = lBase + ((p < 2) ? (ty*4 + p*2) : (64 + ty*4 + (p-2)*2));
#pragma unroll
        for (int j = 0; j < 8; j++) {
            int s = sBase + ((j < 4) ? (tx*4 + j) : (64 + tx*4 + (j-4)));
            if (s >= S) continue;
            float2 r = upk2(acc[p][j]);
            if (l < Lq)     C[(size_t)l * S + s]     = r.x * 0.0625f;
            if (l + 1 < Lq) C[(size_t)(l+1) * S + s] = r.y * 0.0625f;
        }
    }
}

// ---------------------------------------------------------------------------
// Fused omega/theta heads: Com = relu(A@Wom+bom), Cth = tanh(A@Wth+bth)*pi.
// Tile: 64 rows x (16+16) cols, K-step 16.
// ---------------------------------------------------------------------------
__global__ __launch_bounds__(256) void gemm_omth(
    const float* __restrict__ A,
    const float* __restrict__ Wom, const float* __restrict__ bom,
    const float* __restrict__ Wth, const float* __restrict__ bth,
    float* __restrict__ Com, float* __restrict__ Cth, int N)
{
    __shared__ float As[16][68];
    __shared__ float Ws[16][34];
    int tid = threadIdx.x;
    int rowBase = blockIdx.x * 64;
    int ty = tid >> 4, tx = tid & 15;
    float acc[4][2] = {{0.f,0.f},{0.f,0.f},{0.f,0.f},{0.f,0.f}};

    int aRow = tid >> 2;         // 0..63
    int aK   = (tid & 3) * 4;
    int wK   = tid >> 4;         // 0..15
    int wC   = tid & 15;
    bool av = (rowBase + aRow) < N;
    const float* Ap = A + (size_t)(rowBase + aRow) * 512 + aK;

    for (int k0 = 0; k0 < 512; k0 += 16) {
        float4 a = av ? *(const float4*)(Ap + k0) : make_float4(0.f,0.f,0.f,0.f);
        As[aK+0][aRow] = a.x; As[aK+1][aRow] = a.y;
        As[aK+2][aRow] = a.z; As[aK+3][aRow] = a.w;
        Ws[wK][wC]      = Wom[(size_t)(k0 + wK) * 16 + wC];
        Ws[wK][16 + wC] = Wth[(size_t)(k0 + wK) * 16 + wC];
        __syncthreads();
#pragma unroll
        for (int k = 0; k < 16; k++) {
            float4 avv = *(const float4*)&As[k][ty*4];
            float w0 = Ws[k][tx], w1 = Ws[k][16 + tx];
            acc[0][0] = fmaf(avv.x, w0, acc[0][0]); acc[0][1] = fmaf(avv.x, w1, acc[0][1]);
            acc[1][0] = fmaf(avv.y, w0, acc[1][0]); acc[1][1] = fmaf(avv.y, w1, acc[1][1]);
            acc[2][0] = fmaf(avv.z, w0, acc[2][0]); acc[2][1] = fmaf(avv.z, w1, acc[2][1]);
            acc[3][0] = fmaf(avv.w, w0, acc[3][0]); acc[3][1] = fmaf(avv.w, w1, acc[3][1]);
        }
        __syncthreads();
    }
#pragma unroll
    for (int i = 0; i < 4; i++) {
        int row = rowBase + ty*4 + i;
        if (row >= N) continue;
        Com[(size_t)row * 16 + tx] = fmaxf(acc[i][0] + bom[tx], 0.f);
        Cth[(size_t)row * 16 + tx] = tanhf(acc[i][1] + bth[tx]) * PI_F;
    }
}

// ---------------------------------------------------------------------------
// Rotation builders.  Qr/Kr layout: [row, h, m*64 + block*16 + i]
// ---------------------------------------------------------------------------
__global__ void build_qr(const float* __restrict__ Q, const float* __restrict__ om,
                         const float* __restrict__ th, float* __restrict__ Qr,
                         int seq, float invSeq)
{
    int row = blockIdx.x;
    int tid = threadIdx.x;
    int h = tid >> 5, m = (tid >> 4) & 1, i = tid & 15;
    float pos = (float)(row % seq) * invSeq;
    int oi = row * 16 + h * 2 + m;
    float ang = fmaf(om[oi], pos, th[oi]);
    float sn, cs; sincosf(ang, &sn, &cs);
    const float* q = Q + (size_t)row * 512 + h * 64;
    float q0 = q[i], q1 = q[16+i], q2 = q[32+i], q3 = q[48+i];
    float* o = Qr + ((size_t)row * HH + h) * 128 + m * 64;
    o[i]      = q0*cs - q1*sn;
    o[16 + i] = q1*cs + q0*sn;
    o[32 + i] = q2*cs + q3*sn;
    o[48 + i] = q3*cs - q2*sn;
}

__global__ void build_kr(const float* __restrict__ K, const float* __restrict__ om,
                         const float* __restrict__ th, float* __restrict__ Kr,
                         int seq, float invSeq)
{
    int row = blockIdx.x;
    int tid = threadIdx.x;
    int h = tid >> 5, m = (tid >> 4) & 1, i = tid & 15;
    float pos = (float)(row % seq) * invSeq;
    int oi = row * 16 + h * 2 + m;
    float ang = fmaf(om[oi], pos, th[oi]);
    float sn, cs; sincosf(ang, &sn, &cs);
    const float* k = K + (size_t)row * 512 + h * 64;
    float k0 = k[i], k1 = k[16+i], k2 = k[32+i], k3 = k[48+i];
    float* o = Kr + ((size_t)row * HH + h) * 128 + m * 64;
    o[i]      = k0*cs - k2*sn;
    o[16 + i] = k1*cs - k3*sn;
    o[32 + i] = k2*cs + k0*sn;
    o[48 + i] = k3*cs + k1*sn;
}

// ---------------------------------------------------------------------------
// Softmax+AV for large S (layer 0).  One block per (b,h,l).
// ---------------------------------------------------------------------------
__global__ __launch_bounds__(256) void softmax_av(
    const float* __restrict__ scores, const float* __restrict__ V,
    float* __restrict__ out, int Lq, int S)
{
    __shared__ float p[3072];
    __shared__ float red[256];
    int l = blockIdx.x, h = blockIdx.y, b = blockIdx.z;
    int tid = threadIdx.x;
    const float* srow = scores + (((size_t)(b*HH + h) * Lq) + l) * S;

    float lmax = -3.4e38f;
    for (int s = tid; s < S; s += 256) { float v = srow[s]; p[s] = v; lmax = fmaxf(lmax, v); }
    red[tid] = lmax; __syncthreads();
    for (int off = 128; off > 0; off >>= 1) {
        if (tid < off) red[tid] = fmaxf(red[tid], red[tid + off]);
        __syncthreads();
    }
    float mx = red[0]; __syncthreads();

    float lsum = 0.f;
    for (int s = tid; s < S; s += 256) { float e = __expf(p[s] - mx); p[s] = e; lsum += e; }
    red[tid] = lsum; __syncthreads();
    for (int off = 128; off > 0; off >>= 1) {
        if (tid < off) red[tid] += red[tid + off];
        __syncthreads();
    }
    float inv = 1.f / red[0]; __syncthreads();

    int e = tid & 63, gq = tid >> 6;
    float acc = 0.f;
    for (int s = gq; s < S; s += 4)
        acc = fmaf(p[s], V[(((size_t)b*S + s) << 9) + (h << 6) + e], acc);
    red[tid] = acc; __syncthreads();
    if (gq == 0) {
        float r = (red[e] + red[64+e] + red[128+e] + red[192+e]) * inv;
        out[(((size_t)b*Lq + l) << 9) + (h << 6) + e] = r;
    }
}

// ---------------------------------------------------------------------------
// Softmax+AV specialized for S=96 (layer 1).  Block = 32 query rows of one
// (b,h); V tile staged in shared; warp handles 4 rows.
// ---------------------------------------------------------------------------
__global__ __launch_bounds__(256) void softmax_av_s96(
    const float* __restrict__ scores, const float* __restrict__ V,
    float* __restrict__ out, int Lq)
{
    __shared__ float Vs[96 * 64];
    int h = blockIdx.y, b = blockIdx.z;
    int tid = threadIdx.x, wid = tid >> 5, lane = tid & 31;
    const float* Vb = V + ((size_t)b * 96) * 512 + h * 64;
    for (int i = tid; i < 96 * 16; i += 256) {
        int s = i >> 4, c = (i & 15) * 4;
        *(float4*)&Vs[s * 64 + c] = *(const float4*)&Vb[(size_t)s * 512 + c];
    }
    __syncthreads();

    int lBase = blockIdx.x * 32 + wid * 4;
    const float* srow = scores + (((size_t)(b*HH + h) * Lq) + lBase) * 96;
#pragma unroll
    for (int rr = 0; rr < 4; rr++) {
        const float* sr = srow + rr * 96;
        float pr[3];
        pr[0] = sr[lane]; pr[1] = sr[lane + 32]; pr[2] = sr[lane + 64];
        float m = fmaxf(pr[0], fmaxf(pr[1], pr[2]));
#pragma unroll
        for (int off = 16; off > 0; off >>= 1)
            m = fmaxf(m, __shfl_xor_sync(0xffffffffu, m, off));
        pr[0] = __expf(pr[0] - m); pr[1] = __expf(pr[1] - m); pr[2] = __expf(pr[2] - m);
        float ssum = pr[0] + pr[1] + pr[2];
#pragma unroll
        for (int off = 16; off > 0; off >>= 1)
            ssum += __shfl_xor_sync(0xffffffffu, ssum, off);
        float inv = 1.f / ssum;
        float a0 = 0.f, a1 = 0.f;
#pragma unroll
        for (int j = 0; j < 3; j++)
#pragma unroll
            for (int sl = 0; sl < 32; sl++) {
                float ps = __shfl_sync(0xffffffffu, pr[j], sl);
                int s = j * 32 + sl;
                a0 = fmaf(ps, Vs[s * 64 + lane], a0);
                a1 = fmaf(ps, Vs[s * 64 + lane + 32], a1);
            }
        int l = lBase + rr;
        float* ob = out + ((size_t)(b * Lq + l)) * 512 + h * 64;
        ob[lane]      = a0 * inv;
        ob[lane + 32] = a1 * inv;
    }
}

// ---------------------------------------------------------------------------
// Trend norm: series_decomp(25) + LayerNorm(seasonal) + trend
// ---------------------------------------------------------------------------
__global__ __launch_bounds__(256) void trend_norm(
    const float* __restrict__ x, const float* __restrict__ gm,
    const float* __restrict__ bt, float* __restrict__ y)
{
    __shared__ float seas[512];
    __shared__ float trend[512];
    __shared__ float red[256];
    int b = blockIdx.y, t = blockIdx.x, tid = threadIdx.x;
    const float* xb = x + (size_t)b * INDN * 512;
    float ls = 0.f, ls2 = 0.f;
    for (int d = tid; d < 512; d += 256) {
        float tr = 0.f;
#pragma unroll
        for (int j = -12; j <= 12; j++) {
            int tt = t + j;
            tt = tt < 0 ? 0 : (tt > INDN-1 ? INDN-1 : tt);
            tr += xb[(size_t)tt * 512 + d];
        }
        tr *= (1.0f / 25.0f);
        float sv = xb[(size_t)t * 512 + d] - tr;
        seas[d] = sv; trend[d] = tr;
        ls += sv; ls2 += sv * sv;
    }
    red[tid] = ls; __syncthreads();
    for (int off = 128; off > 0; off >>= 1) { if (tid < off) red[tid] += red[tid+off]; __syncthreads(); }
    float mu = red[0] * (1.f/512.f); __syncthreads();
    red[tid] = ls2; __syncthreads();
    for (int off = 128; off > 0; off >>= 1) { if (tid < off) red[tid] += red[tid+off]; __syncthreads(); }
    float var = red[0] * (1.f/512.f) - mu*mu;
    float rs = rsqrtf(var + 1e-5f);
    for (int d = tid; d < 512; d += 256)
        y[((size_t)b*INDN + t) * 512 + d] = (seas[d] - mu) * rs * gm[d] + bt[d] + trend[d];
}

// ---------------------------------------------------------------------------
// Penalties
// ---------------------------------------------------------------------------
__global__ void zero_pen() { g_pen[0] = 0.f; g_pen[1] = 0.f; }

__global__ __launch_bounds__(256) void penalty_kernel(
    const float* __restrict__ om, const float* __restrict__ th,
    int total, int seq, float scale)
{
    float omp = 0.f, thp = 0.f;
    for (int idx = blockIdx.x * 256 + threadIdx.x; idx < total; idx += gridDim.x * 256) {
        int n = idx >> 4;
        int sIn = n % seq;
        float t = th[idx]; thp += t * t;
        if (sIn < seq - 1) { float d = om[idx + 16] - om[idx]; omp += d * d; }
    }
#pragma unroll
    for (int o = 16; o > 0; o >>= 1) {
        omp += __shfl_down_sync(0xffffffffu, omp, o);
        thp += __shfl_down_sync(0xffffffffu, thp, o);
    }
    __shared__ float sho[8], sht[8];
    int wid = threadIdx.x >> 5, lid = threadIdx.x & 31;
    if (lid == 0) { sho[wid] = omp; sht[wid] = thp; }
    __syncthreads();
    if (threadIdx.x == 0) {
        float so = 0.f, st = 0.f;
        for (int w = 0; w < 8; w++) { so += sho[w]; st += sht[w]; }
        atomicAdd(&g_pen[0], so * scale);
        atomicAdd(&g_pen[1], st * scale);
    }
}

__global__ void finalize_kernel(float* out, int out_size)
{
    if (out_size >= BLD + 2) {
        out[BLD]     = g_pen[0];
        out[BLD + 1] = g_pen[1];
    }
}

// ---------------------------------------------------------------------------
// Host launcher
// ---------------------------------------------------------------------------
#define SYMADDR(p, s) do { void* _t = nullptr; cudaGetSymbolAddress(&_t, s); (p) = (float*)_t; } while (0)

extern "C" void kernel_launch(void* const* d_in, const int* in_sizes, int n_in,
                              void* d_out, int out_size)
{
    (void)in_sizes; (void)n_in;
    const float* queries = (const float*)d_in[0];
    const float* keys    = (const float*)d_in[1];
    const float* values  = (const float*)d_in[2];
    const float* Wq  = (const float*)d_in[3];
    const float* bq  = (const float*)d_in[4];
    const float* Wk  = (const float*)d_in[5];
    const float* bk  = (const float*)d_in[6];
    const float* Wv  = (const float*)d_in[7];
    const float* bv  = (const float*)d_in[8];
    const float* Wqo = (const float*)d_in[9];
    const float* bqo = (const float*)d_in[10];
    const float* Wko = (const float*)d_in[11];
    const float* bko = (const float*)d_in[12];
    const float* Wqt = (const float*)d_in[13];
    const float* bqt = (const float*)d_in[14];
    const float* Wkt = (const float*)d_in[15];
    const float* bkt = (const float*)d_in[16];
    const float* Wo  = (const float*)d_in[17];
    const float* bo  = (const float*)d_in[18];
    const float* Ibuf = (const float*)d_in[19];
    const float* ln_g = (const float*)d_in[20];
    const float* ln_b = (const float*)d_in[21];
    float* out = (float*)d_out;

    const int NBS = BB * SS;      // 24576
    const int NBI = BB * INDN;    // 768
    const int W2  = 512 * 512;
    const int W2S = 512 * 16;

    float *pK0, *pV0, *pQ0, *pkom0, *pkth0, *pqom0, *pqth0, *pQr0, *pKr0, *pScores;
    float *pAttn0, *pIndB, *pIndC, *pQ1, *pK1, *pV1, *pqom1, *pqth1, *pkom1, *pkth1;
    float *pQr1, *pKr1, *pAttn1;
    SYMADDR(pK0, g_K0);     SYMADDR(pV0, g_V0);     SYMADDR(pQ0, g_Q0);
    SYMADDR(pkom0, g_kom0); SYMADDR(pkth0, g_kth0);
    SYMADDR(pqom0, g_qom0); SYMADDR(pqth0, g_qth0);
    SYMADDR(pQr0, g_Qr0);   SYMADDR(pKr0, g_Kr0);   SYMADDR(pScores, g_scores);
    SYMADDR(pAttn0, g_attn0); SYMADDR(pIndB, g_indB); SYMADDR(pIndC, g_indC);
    SYMADDR(pQ1, g_Q1);     SYMADDR(pK1, g_K1);     SYMADDR(pV1, g_V1);
    SYMADDR(pqom1, g_qom1); SYMADDR(pqth1, g_qth1);
    SYMADDR(pkom1, g_kom1); SYMADDR(pkth1, g_kth1);
    SYMADDR(pQr1, g_Qr1);   SYMADDR(pKr1, g_Kr1);   SYMADDR(pAttn1, g_attn1);

    // ------------------------ Layer 0 (inducings x keys/values) -------------
    gemm_nn<<<dim3(4, 192), 256>>>(keys,   Wk, bk, pK0, NBS, 512);
    gemm_nn<<<dim3(4, 192), 256>>>(values, Wv, bv, pV0, NBS, 512);
    gemm_nn<<<dim3(4, 1),   256>>>(Ibuf,   Wq, bq, pQ0, INDN, 512);

    gemm_omth<<<NBS/64, 256>>>(keys, Wko, bko, Wkt, bkt, pkom0, pkth0, NBS);
    gemm_omth<<<(INDN+63)/64, 256>>>(Ibuf, Wqo, bqo, Wqt, bqt, pqom0, pqth0, INDN);

    zero_pen<<<1, 1>>>();
    penalty_kernel<<<6, 256>>>(pqom0, pqth0, INDN*16, INDN, (float)BB);
    penalty_kernel<<<1024, 256>>>(pkom0, pkth0, NBS*16, SS, 1.f);

    build_qr<<<INDN, 256>>>(pQ0, pqom0, pqth0, pQr0, INDN, 1.f/INDN);
    build_kr<<<NBS,  256>>>(pK0, pkom0, pkth0, pKr0, SS,   1.f/SS);

    gemm_nt<<<dim3(SS/128, 1, BB*HH), 256>>>(pQr0, (size_t)0, pKr0, pScores, INDN, SS);
    softmax_av<<<dim3(INDN, HH, BB), 256>>>(pScores, pV0, pAttn0, INDN, SS);

    gemm_nn<<<dim3(4, 6), 256>>>(pAttn0, Wo, bo, pIndB, NBI, 512);
    trend_norm<<<dim3(INDN, BB), 256>>>(pIndB, ln_g, ln_b, pIndC);

    // ------------------------ Layer 1 (queries x inducings) -----------------
    gemm_nn<<<dim3(4, 192), 256>>>(queries, Wq + W2, bq + 512, pQ1, NBS, 512);
    gemm_nn<<<dim3(4, 6),   256>>>(pIndC,   Wk + W2, bk + 512, pK1, NBI, 512);
    gemm_nn<<<dim3(4, 6),   256>>>(pIndC,   Wv + W2, bv + 512, pV1, NBI, 512);

    gemm_omth<<<NBS/64, 256>>>(queries, Wqo + W2S, bqo + 16, Wqt + W2S, bqt + 16,
                               pqom1, pqth1, NBS);
    gemm_omth<<<NBI/64, 256>>>(pIndC, Wko + W2S, bko + 16, Wkt + W2S, bkt + 16,
                               pkom1, pkth1, NBI);

    penalty_kernel<<<1024, 256>>>(pqom1, pqth1, NBS*16, LL, 1.f);
    penalty_kernel<<<48, 256>>>(pkom1, pkth1, NBI*16, INDN, 1.f);

    build_qr<<<NBS, 256>>>(pQ1, pqom1, pqth1, pQr1, LL,   1.f/LL);
    build_kr<<<NBI, 256>>>(pK1, pkom1, pkth1, pKr1, INDN, 1.f/INDN);

    gemm_nt<<<dim3(1, LL/128, BB*HH), 256>>>(pQr1, (size_t)LL*HH*128, pKr1, pScores, LL, INDN);
    softmax_av_s96<<<dim3(LL/32, HH, BB), 256>>>(pScores, pV1, pAttn1, LL);

    gemm_nn<<<dim3(4, 192), 256>>>(pAttn1, Wo + W2, bo + 512, out, NBS, 512);

    finalize_kernel<<<1, 1>>>(out, out_size);
}

// round 7
// speedup vs baseline: 1.8086x; 1.2026x over previous
#include <cuda_runtime.h>
#include <cuda_bf16.h>
#include <math.h>
#include <stdint.h>

// Problem constants
#define BB   8
#define LL   3072
#define SS   3072
#define DD   512
#define HH   8
#define INDN 96
#define BLD  (BB*LL*DD)   // 12582912
#define PI_F 3.14159265358979323846f

// ---------------------------------------------------------------------------
// Scratch (device globals; allocation-free per harness rules)
// ---------------------------------------------------------------------------
__device__ float g_K0   [(size_t)BB*SS*DD];
__device__ float g_V0   [(size_t)BB*SS*DD];
__device__ float g_Q0   [(size_t)INDN*DD];
__device__ float g_kom0 [(size_t)BB*SS*16];
__device__ float g_kth0 [(size_t)BB*SS*16];
__device__ float g_qom0 [(size_t)INDN*16];
__device__ float g_qth0 [(size_t)INDN*16];
__device__ float g_scores[(size_t)BB*HH*INDN*SS];  // 75.5MB, reused by layer 1
__device__ float g_attn0[(size_t)BB*INDN*DD];
__device__ float g_indB [(size_t)BB*INDN*DD];
__device__ float g_indC [(size_t)BB*INDN*DD];
__device__ float g_Q1   [(size_t)BB*LL*DD];
__device__ float g_K1   [(size_t)BB*INDN*DD];
__device__ float g_V1   [(size_t)BB*INDN*DD];
__device__ float g_qom1 [(size_t)BB*LL*16];
__device__ float g_qth1 [(size_t)BB*LL*16];
__device__ float g_kom1 [(size_t)BB*INDN*16];
__device__ float g_kth1 [(size_t)BB*INDN*16];
__device__ float g_attn1[(size_t)BB*LL*DD];
__device__ float g_pen[2];
// bf16 split buffers
__device__ __nv_bfloat16 g_ahi [(size_t)BB*SS*DD];      // A operand (reused)
__device__ __nv_bfloat16 g_alo [(size_t)BB*SS*DD];
__device__ __nv_bfloat16 g_wThi[(size_t)DD*DD];         // W^T operand
__device__ __nv_bfloat16 g_wTlo[(size_t)DD*DD];
__device__ __nv_bfloat16 g_qrh [(size_t)BB*LL*HH*128];  // rotated Q hi/lo
__device__ __nv_bfloat16 g_qrl [(size_t)BB*LL*HH*128];
__device__ __nv_bfloat16 g_krh [(size_t)BB*SS*HH*128];  // rotated K hi/lo
__device__ __nv_bfloat16 g_krl [(size_t)BB*SS*HH*128];

// ---------------------------------------------------------------------------
// Packed f32x2 helpers (FFMA2 path for small exact-fp32 GEMMs)
// ---------------------------------------------------------------------------
__device__ __forceinline__ unsigned long long pk2(float x, float y) {
    unsigned long long r;
    asm("mov.b64 %0, {%1, %2};" : "=l"(r) : "f"(x), "f"(y));
    return r;
}
__device__ __forceinline__ void fma2(unsigned long long& d,
                                     unsigned long long a, unsigned long long b) {
    asm("fma.rn.f32x2 %0, %1, %2, %0;" : "+l"(d) : "l"(a), "l"(b));
}
__device__ __forceinline__ float2 upk2(unsigned long long v) {
    float2 r;
    asm("mov.b64 {%0, %1}, %2;" : "=f"(r.x), "=f"(r.y) : "l"(v));
    return r;
}

// ---------------------------------------------------------------------------
// bf16 mma helper (baseline PTX, sm_80+)
// ---------------------------------------------------------------------------
__device__ __forceinline__ void mma_bf16(float* c, const uint32_t* a, const uint32_t* b) {
    asm volatile(
        "mma.sync.aligned.m16n8k16.row.col.f32.bf16.bf16.f32 "
        "{%0,%1,%2,%3}, {%4,%5,%6,%7}, {%8,%9}, {%0,%1,%2,%3};"
        : "+f"(c[0]), "+f"(c[1]), "+f"(c[2]), "+f"(c[3])
        : "r"(a[0]), "r"(a[1]), "r"(a[2]), "r"(a[3]), "r"(b[0]), "r"(b[1]));
}

// ---------------------------------------------------------------------------
// mma_nn_bf16: C[N,512] = (Ahi+Alo)[N,512] @ (WThi+WTlo)^T + bias
// A row-major [N][512] bf16, WT [n][k] bf16.  3-term split accumulation.
// Block tile 128x128, 8 warps (2x4), warp 64x32, kc=32 (16 k-pairs).
// SMEM: [128 rows][20 u32] per array (16 pairs + 4 pad; conflict-free frags).
// ---------------------------------------------------------------------------
__global__ __launch_bounds__(256) void mma_nn_bf16(
    const __nv_bfloat16* __restrict__ Ahi, const __nv_bfloat16* __restrict__ Alo,
    const __nv_bfloat16* __restrict__ Bhi, const __nv_bfloat16* __restrict__ Blo,
    const float* __restrict__ bias, float* __restrict__ C, int N)
{
    __shared__ uint32_t AsH[128 * 20], AsL[128 * 20];
    __shared__ uint32_t BsH[128 * 20], BsL[128 * 20];
    int tid = threadIdx.x;
    int rowBase = blockIdx.y * 128, colBase = blockIdx.x * 128;
    int wid = tid >> 5, lane = tid & 31;
    int mBase = (wid >> 2) * 64, nBase = (wid & 3) * 32;

    float c[4][4][4];
#pragma unroll
    for (int ma = 0; ma < 4; ma++)
#pragma unroll
        for (int na = 0; na < 4; na++)
#pragma unroll
            for (int i = 0; i < 4; i++) c[ma][na][i] = 0.f;

    for (int k0 = 0; k0 < 512; k0 += 32) {
        // stage: 128 rows x 32 k (4 uint4 per row per array); 2 loads/thread/array
#pragma unroll
        for (int j = 0; j < 2; j++) {
            int i = tid + j * 256;
            int row = i >> 2, seg = i & 3;
            int gr = rowBase + row;
            size_t ga = (size_t)gr * 512 + k0 + seg * 8;
            uint4 vh = (gr < N) ? *(const uint4*)(Ahi + ga) : make_uint4(0,0,0,0);
            uint4 vl = (gr < N) ? *(const uint4*)(Alo + ga) : make_uint4(0,0,0,0);
            *(uint4*)&AsH[row * 20 + seg * 4] = vh;
            *(uint4*)&AsL[row * 20 + seg * 4] = vl;
            size_t gb = (size_t)(colBase + row) * 512 + k0 + seg * 8;
            *(uint4*)&BsH[row * 20 + seg * 4] = *(const uint4*)(Bhi + gb);
            *(uint4*)&BsL[row * 20 + seg * 4] = *(const uint4*)(Blo + gb);
        }
        __syncthreads();
#pragma unroll
        for (int kk = 0; kk < 16; kk += 8) {
            int kq = kk + (lane & 3);
            uint32_t bh[4][2], bl[4][2];
#pragma unroll
            for (int na = 0; na < 4; na++) {
                int n = nBase + na * 8 + (lane >> 2);
                bh[na][0] = BsH[n * 20 + kq];     bh[na][1] = BsH[n * 20 + kq + 4];
                bl[na][0] = BsL[n * 20 + kq];     bl[na][1] = BsL[n * 20 + kq + 4];
            }
#pragma unroll
            for (int ma = 0; ma < 4; ma++) {
                int r = mBase + ma * 16 + (lane >> 2);
                uint32_t ah[4], al[4];
                ah[0] = AsH[r * 20 + kq];       ah[1] = AsH[(r + 8) * 20 + kq];
                ah[2] = AsH[r * 20 + kq + 4];   ah[3] = AsH[(r + 8) * 20 + kq + 4];
                al[0] = AsL[r * 20 + kq];       al[1] = AsL[(r + 8) * 20 + kq];
                al[2] = AsL[r * 20 + kq + 4];   al[3] = AsL[(r + 8) * 20 + kq + 4];
#pragma unroll
                for (int na = 0; na < 4; na++) {
                    mma_bf16(c[ma][na], ah, bh[na]);
                    mma_bf16(c[ma][na], ah, bl[na]);
                    mma_bf16(c[ma][na], al, bh[na]);
                }
            }
        }
        __syncthreads();
    }

#pragma unroll
    for (int ma = 0; ma < 4; ma++) {
        int row0 = rowBase + mBase + ma * 16 + (lane >> 2);
        int row1 = row0 + 8;
#pragma unroll
        for (int na = 0; na < 4; na++) {
            int col = colBase + nBase + na * 8 + (lane & 3) * 2;
            float b0 = bias[col], b1 = bias[col + 1];
            if (row0 < N) {
                float2 o = make_float2(c[ma][na][0] + b0, c[ma][na][1] + b1);
                *(float2*)(C + (size_t)row0 * 512 + col) = o;
            }
            if (row1 < N) {
                float2 o = make_float2(c[ma][na][2] + b0, c[ma][na][3] + b1);
                *(float2*)(C + (size_t)row1 * 512 + col) = o;
            }
        }
    }
}

// ---------------------------------------------------------------------------
// mma_nt_bf16: scores[bh,l,s] = (1/16) * Qr[l,:].Kr[s,:]  per (b,h), K=128.
// Qr/Kr in bf16 hi/lo, layout [row][h][128] (fixed h: row stride 1024 elems).
// ---------------------------------------------------------------------------
__global__ __launch_bounds__(256) void mma_nt_bf16(
    const __nv_bfloat16* __restrict__ Qh, const __nv_bfloat16* __restrict__ Ql,
    size_t qBstride,
    const __nv_bfloat16* __restrict__ Kh, const __nv_bfloat16* __restrict__ Kl,
    float* __restrict__ scores, int Lq, int S)
{
    __shared__ uint32_t AsH[128 * 20], AsL[128 * 20];
    __shared__ uint32_t BsH[128 * 20], BsL[128 * 20];
    int tid = threadIdx.x;
    int bh = blockIdx.z, b = bh >> 3, h = bh & 7;
    size_t aOff = (size_t)b * qBstride + (size_t)h * 128;
    size_t bOff = ((size_t)b * S * HH + h) * 128;
    float* C = scores + (size_t)bh * Lq * S;
    int lBase = blockIdx.y * 128, sBase = blockIdx.x * 128;
    int wid = tid >> 5, lane = tid & 31;
    int mBase = (wid >> 2) * 64, nBase = (wid & 3) * 32;

    float c[4][4][4];
#pragma unroll
    for (int ma = 0; ma < 4; ma++)
#pragma unroll
        for (int na = 0; na < 4; na++)
#pragma unroll
            for (int i = 0; i < 4; i++) c[ma][na][i] = 0.f;

    for (int k0 = 0; k0 < 128; k0 += 32) {
#pragma unroll
        for (int j = 0; j < 2; j++) {
            int i = tid + j * 256;
            int row = i >> 2, seg = i & 3;
            int gl = lBase + row;
            size_t ga = aOff + (size_t)gl * 1024 + k0 + seg * 8;
            uint4 vh = (gl < Lq) ? *(const uint4*)(Qh + ga) : make_uint4(0,0,0,0);
            uint4 vl = (gl < Lq) ? *(const uint4*)(Ql + ga) : make_uint4(0,0,0,0);
            *(uint4*)&AsH[row * 20 + seg * 4] = vh;
            *(uint4*)&AsL[row * 20 + seg * 4] = vl;
            int gs = sBase + row;
            size_t gb = bOff + (size_t)gs * 1024 + k0 + seg * 8;
            uint4 wh = (gs < S) ? *(const uint4*)(Kh + gb) : make_uint4(0,0,0,0);
            uint4 wl = (gs < S) ? *(const uint4*)(Kl + gb) : make_uint4(0,0,0,0);
            *(uint4*)&BsH[row * 20 + seg * 4] = wh;
            *(uint4*)&BsL[row * 20 + seg * 4] = wl;
        }
        __syncthreads();
#pragma unroll
        for (int kk = 0; kk < 16; kk += 8) {
            int kq = kk + (lane & 3);
            uint32_t bhf[4][2], blf[4][2];
#pragma unroll
            for (int na = 0; na < 4; na++) {
                int n = nBase + na * 8 + (lane >> 2);
                bhf[na][0] = BsH[n * 20 + kq];  bhf[na][1] = BsH[n * 20 + kq + 4];
                blf[na][0] = BsL[n * 20 + kq];  blf[na][1] = BsL[n * 20 + kq + 4];
            }
#pragma unroll
            for (int ma = 0; ma < 4; ma++) {
                int r = mBase + ma * 16 + (lane >> 2);
                uint32_t ah[4], al[4];
                ah[0] = AsH[r * 20 + kq];       ah[1] = AsH[(r + 8) * 20 + kq];
                ah[2] = AsH[r * 20 + kq + 4];   ah[3] = AsH[(r + 8) * 20 + kq + 4];
                al[0] = AsL[r * 20 + kq];       al[1] = AsL[(r + 8) * 20 + kq];
                al[2] = AsL[r * 20 + kq + 4];   al[3] = AsL[(r + 8) * 20 + kq + 4];
#pragma unroll
                for (int na = 0; na < 4; na++) {
                    mma_bf16(c[ma][na], ah, bhf[na]);
                    mma_bf16(c[ma][na], ah, blf[na]);
                    mma_bf16(c[ma][na], al, bhf[na]);
                }
            }
        }
        __syncthreads();
    }

#pragma unroll
    for (int ma = 0; ma < 4; ma++) {
        int l0 = lBase + mBase + ma * 16 + (lane >> 2);
        int l1 = l0 + 8;
#pragma unroll
        for (int na = 0; na < 4; na++) {
            int s = sBase + nBase + na * 8 + (lane & 3) * 2;
            if (s + 1 < S) {
                if (l0 < Lq) {
                    float2 o = make_float2(c[ma][na][0] * 0.0625f, c[ma][na][1] * 0.0625f);
                    *(float2*)(C + (size_t)l0 * S + s) = o;
                }
                if (l1 < Lq) {
                    float2 o = make_float2(c[ma][na][2] * 0.0625f, c[ma][na][3] * 0.0625f);
                    *(float2*)(C + (size_t)l1 * S + s) = o;
                }
            } else if (s < S) {
                if (l0 < Lq) C[(size_t)l0 * S + s] = c[ma][na][0] * 0.0625f;
                if (l1 < Lq) C[(size_t)l1 * S + s] = c[ma][na][2] * 0.0625f;
            }
        }
    }
}

// ---------------------------------------------------------------------------
// Split fp32 -> (hi, lo) bf16 contiguous
// ---------------------------------------------------------------------------
__global__ __launch_bounds__(256) void split_f32(
    const float* __restrict__ x, __nv_bfloat16* __restrict__ hi,
    __nv_bfloat16* __restrict__ lo, int n4)
{
    for (int i = blockIdx.x * 256 + threadIdx.x; i < n4; i += gridDim.x * 256) {
        float4 v = ((const float4*)x)[i];
        __nv_bfloat16 h0 = __float2bfloat16(v.x);
        __nv_bfloat16 h1 = __float2bfloat16(v.y);
        __nv_bfloat16 h2 = __float2bfloat16(v.z);
        __nv_bfloat16 h3 = __float2bfloat16(v.w);
        __nv_bfloat162* hp = (__nv_bfloat162*)hi;
        __nv_bfloat162* lp = (__nv_bfloat162*)lo;
        hp[2*i]   = __nv_bfloat162(h0, h1);
        hp[2*i+1] = __nv_bfloat162(h2, h3);
        lp[2*i]   = __nv_bfloat162(__float2bfloat16(v.x - __bfloat162float(h0)),
                                   __float2bfloat16(v.y - __bfloat162float(h1)));
        lp[2*i+1] = __nv_bfloat162(__float2bfloat16(v.z - __bfloat162float(h2)),
                                   __float2bfloat16(v.w - __bfloat162float(h3)));
    }
}

// ---------------------------------------------------------------------------
// Split + transpose W[512,512] -> WT hi/lo with WT[n][k] = W[k][n]
// ---------------------------------------------------------------------------
__global__ __launch_bounds__(256) void split_wT(
    const float* __restrict__ W, __nv_bfloat16* __restrict__ hiT,
    __nv_bfloat16* __restrict__ loT)
{
    __shared__ float t[32][33];
    int bn = blockIdx.x * 32;
    int bk = blockIdx.y * 32;
    int tx = threadIdx.x & 31, ty = threadIdx.x >> 5;
    for (int r = ty; r < 32; r += 8)
        t[r][tx] = W[(size_t)(bk + r) * 512 + bn + tx];
    __syncthreads();
    for (int r = ty; r < 32; r += 8) {
        float v = t[tx][r];
        __nv_bfloat16 h = __float2bfloat16(v);
        size_t o = (size_t)(bn + r) * 512 + bk + tx;
        hiT[o] = h;
        loT[o] = __float2bfloat16(v - __bfloat162float(h));
    }
}

// ---------------------------------------------------------------------------
// FFMA2 GEMM (NN) for small exact-fp32 GEMMs
// ---------------------------------------------------------------------------
__global__ __launch_bounds__(256, 2) void gemm_nn(
    const float* __restrict__ A, const float* __restrict__ W,
    const float* __restrict__ bias, float* __restrict__ C, int N, int P)
{
    __shared__ float As[16][132];
    __shared__ float Bs[16][132];
    int tid = threadIdx.x;
    int rowBase = blockIdx.y * 128;
    int colBase = blockIdx.x * 128;
    int ty = tid >> 4, tx = tid & 15;

    unsigned long long acc[4][8];
#pragma unroll
    for (int p = 0; p < 4; p++)
#pragma unroll
        for (int j = 0; j < 8; j++) acc[p][j] = 0ull;

    int aRow = tid >> 2;
    int aK   = (tid & 3) * 4;
    int bK   = tid >> 4;
    int bCol = (tid & 15) * 4;
    bool v0 = (rowBase + aRow) < N;
    bool v1 = (rowBase + aRow + 64) < N;
    const float* Ap0 = A + (size_t)(rowBase + aRow) * 512 + aK;
    const float* Ap1 = Ap0 + (size_t)64 * 512;
    const float* Wp  = W + (size_t)bK * P + colBase + bCol;

    for (int k0 = 0; k0 < 512; k0 += 16) {
        float4 a0 = v0 ? *(const float4*)(Ap0 + k0) : make_float4(0.f,0.f,0.f,0.f);
        float4 a1 = v1 ? *(const float4*)(Ap1 + k0) : make_float4(0.f,0.f,0.f,0.f);
        As[aK+0][aRow] = a0.x; As[aK+1][aRow] = a0.y;
        As[aK+2][aRow] = a0.z; As[aK+3][aRow] = a0.w;
        As[aK+0][aRow+64] = a1.x; As[aK+1][aRow+64] = a1.y;
        As[aK+2][aRow+64] = a1.z; As[aK+3][aRow+64] = a1.w;
        float4 b0 = *(const float4*)(Wp + (size_t)k0 * P);
        float4 b1 = *(const float4*)(Wp + (size_t)k0 * P + 64);
        *(float4*)&Bs[bK][bCol]      = b0;
        *(float4*)&Bs[bK][bCol + 64] = b1;
        __syncthreads();
#pragma unroll
        for (int k = 0; k < 16; k++) {
            float4 av0 = *(const float4*)&As[k][ty*4];
            float4 av1 = *(const float4*)&As[k][64 + ty*4];
            float4 bv0 = *(const float4*)&Bs[k][tx*4];
            float4 bv1 = *(const float4*)&Bs[k][64 + tx*4];
            unsigned long long ap[4];
            ap[0] = pk2(av0.x, av0.y); ap[1] = pk2(av0.z, av0.w);
            ap[2] = pk2(av1.x, av1.y); ap[3] = pk2(av1.z, av1.w);
            unsigned long long bd[8];
            bd[0] = pk2(bv0.x, bv0.x); bd[1] = pk2(bv0.y, bv0.y);
            bd[2] = pk2(bv0.z, bv0.z); bd[3] = pk2(bv0.w, bv0.w);
            bd[4] = pk2(bv1.x, bv1.x); bd[5] = pk2(bv1.y, bv1.y);
            bd[6] = pk2(bv1.z, bv1.z); bd[7] = pk2(bv1.w, bv1.w);
#pragma unroll
            for (int p = 0; p < 4; p++)
#pragma unroll
                for (int j = 0; j < 8; j++)
                    fma2(acc[p][j], ap[p], bd[j]);
        }
        __syncthreads();
    }

#pragma unroll
    for (int p = 0; p < 4; p++) {
        int row = rowBase + ((p < 2) ? (ty*4 + p*2) : (64 + ty*4 + (p-2)*2));
#pragma unroll
        for (int j = 0; j < 8; j++) {
            int col = colBase + ((j < 4) ? (tx*4 + j) : (64 + tx*4 + (j-4)));
            float2 r = upk2(acc[p][j]);
            float bb = bias[col];
            if (row < N)     C[(size_t)row * P + col]     = r.x + bb;
            if (row + 1 < N) C[(size_t)(row+1) * P + col] = r.y + bb;
        }
    }
}

// ---------------------------------------------------------------------------
// Fused omega/theta heads
// ---------------------------------------------------------------------------
__global__ __launch_bounds__(256) void gemm_omth(
    const float* __restrict__ A,
    const float* __restrict__ Wom, const float* __restrict__ bom,
    const float* __restrict__ Wth, const float* __restrict__ bth,
    float* __restrict__ Com, float* __restrict__ Cth, int N)
{
    __shared__ float As[16][68];
    __shared__ float Ws[16][34];
    int tid = threadIdx.x;
    int rowBase = blockIdx.x * 64;
    int ty = tid >> 4, tx = tid & 15;
    float acc[4][2] = {{0.f,0.f},{0.f,0.f},{0.f,0.f},{0.f,0.f}};

    int aRow = tid >> 2;
    int aK   = (tid & 3) * 4;
    int wK   = tid >> 4;
    int wC   = tid & 15;
    bool av = (rowBase + aRow) < N;
    const float* Ap = A + (size_t)(rowBase + aRow) * 512 + aK;

    for (int k0 = 0; k0 < 512; k0 += 16) {
        float4 a = av ? *(const float4*)(Ap + k0) : make_float4(0.f,0.f,0.f,0.f);
        As[aK+0][aRow] = a.x; As[aK+1][aRow] = a.y;
        As[aK+2][aRow] = a.z; As[aK+3][aRow] = a.w;
        Ws[wK][wC]      = Wom[(size_t)(k0 + wK) * 16 + wC];
        Ws[wK][16 + wC] = Wth[(size_t)(k0 + wK) * 16 + wC];
        __syncthreads();
#pragma unroll
        for (int k = 0; k < 16; k++) {
            float4 avv = *(const float4*)&As[k][ty*4];
            float w0 = Ws[k][tx], w1 = Ws[k][16 + tx];
            acc[0][0] = fmaf(avv.x, w0, acc[0][0]); acc[0][1] = fmaf(avv.x, w1, acc[0][1]);
            acc[1][0] = fmaf(avv.y, w0, acc[1][0]); acc[1][1] = fmaf(avv.y, w1, acc[1][1]);
            acc[2][0] = fmaf(avv.z, w0, acc[2][0]); acc[2][1] = fmaf(avv.z, w1, acc[2][1]);
            acc[3][0] = fmaf(avv.w, w0, acc[3][0]); acc[3][1] = fmaf(avv.w, w1, acc[3][1]);
        }
        __syncthreads();
    }
#pragma unroll
    for (int i = 0; i < 4; i++) {
        int row = rowBase + ty*4 + i;
        if (row >= N) continue;
        Com[(size_t)row * 16 + tx] = fmaxf(acc[i][0] + bom[tx], 0.f);
        Cth[(size_t)row * 16 + tx] = tanhf(acc[i][1] + bth[tx]) * PI_F;
    }
}

// ---------------------------------------------------------------------------
// Rotation builders -> bf16 hi/lo.  Layout [row][h][m*64 + blk*16 + i]
// ---------------------------------------------------------------------------
__device__ __forceinline__ void wr_split(__nv_bfloat16* hi, __nv_bfloat16* lo,
                                         int idx, float v) {
    __nv_bfloat16 h = __float2bfloat16(v);
    hi[idx] = h;
    lo[idx] = __float2bfloat16(v - __bfloat162float(h));
}

__global__ void build_qr(const float* __restrict__ Q, const float* __restrict__ om,
                         const float* __restrict__ th,
                         __nv_bfloat16* __restrict__ Qh, __nv_bfloat16* __restrict__ Ql,
                         int seq, float invSeq)
{
    int row = blockIdx.x;
    int tid = threadIdx.x;
    int h = tid >> 5, m = (tid >> 4) & 1, i = tid & 15;
    float pos = (float)(row % seq) * invSeq;
    int oi = row * 16 + h * 2 + m;
    float ang = fmaf(om[oi], pos, th[oi]);
    float sn, cs; sincosf(ang, &sn, &cs);
    const float* q = Q + (size_t)row * 512 + h * 64;
    float q0 = q[i], q1 = q[16+i], q2 = q[32+i], q3 = q[48+i];
    int o = ((row * HH + h) * 128) + m * 64;
    wr_split(Qh, Ql, o + i,      q0*cs - q1*sn);
    wr_split(Qh, Ql, o + 16 + i, q1*cs + q0*sn);
    wr_split(Qh, Ql, o + 32 + i, q2*cs + q3*sn);
    wr_split(Qh, Ql, o + 48 + i, q3*cs - q2*sn);
}

__global__ void build_kr(const float* __restrict__ K, const float* __restrict__ om,
                         const float* __restrict__ th,
                         __nv_bfloat16* __restrict__ Kh, __nv_bfloat16* __restrict__ Kl,
                         int seq, float invSeq)
{
    int row = blockIdx.x;
    int tid = threadIdx.x;
    int h = tid >> 5, m = (tid >> 4) & 1, i = tid & 15;
    float pos = (float)(row % seq) * invSeq;
    int oi = row * 16 + h * 2 + m;
    float ang = fmaf(om[oi], pos, th[oi]);
    float sn, cs; sincosf(ang, &sn, &cs);
    const float* k = K + (size_t)row * 512 + h * 64;
    float k0 = k[i], k1 = k[16+i], k2 = k[32+i], k3 = k[48+i];
    int o = ((row * HH + h) * 128) + m * 64;
    wr_split(Kh, Kl, o + i,      k0*cs - k2*sn);
    wr_split(Kh, Kl, o + 16 + i, k1*cs - k3*sn);
    wr_split(Kh, Kl, o + 32 + i, k2*cs + k0*sn);
    wr_split(Kh, Kl, o + 48 + i, k3*cs + k1*sn);
}

// ---------------------------------------------------------------------------
// Softmax+AV (layer 0, S=3072)
// ---------------------------------------------------------------------------
__global__ __launch_bounds__(256) void softmax_av(
    const float* __restrict__ scores, const float* __restrict__ V,
    float* __restrict__ out, int Lq, int S)
{
    __shared__ float p[3072];
    __shared__ float red[256];
    int l = blockIdx.x, h = blockIdx.y, b = blockIdx.z;
    int tid = threadIdx.x;
    const float* srow = scores + (((size_t)(b*HH + h) * Lq) + l) * S;

    float lmax = -3.4e38f;
    for (int s = tid; s < S; s += 256) { float v = srow[s]; p[s] = v; lmax = fmaxf(lmax, v); }
    red[tid] = lmax; __syncthreads();
    for (int off = 128; off > 0; off >>= 1) {
        if (tid < off) red[tid] = fmaxf(red[tid], red[tid + off]);
        __syncthreads();
    }
    float mx = red[0]; __syncthreads();

    float lsum = 0.f;
    for (int s = tid; s < S; s += 256) { float e = __expf(p[s] - mx); p[s] = e; lsum += e; }
    red[tid] = lsum; __syncthreads();
    for (int off = 128; off > 0; off >>= 1) {
        if (tid < off) red[tid] += red[tid + off];
        __syncthreads();
    }
    float inv = 1.f / red[0]; __syncthreads();

    int e = tid & 63, gq = tid >> 6;
    float acc = 0.f;
    for (int s = gq; s < S; s += 4)
        acc = fmaf(p[s], V[(((size_t)b*S + s) << 9) + (h << 6) + e], acc);
    red[tid] = acc; __syncthreads();
    if (gq == 0) {
        float r = (red[e] + red[64+e] + red[128+e] + red[192+e]) * inv;
        out[(((size_t)b*Lq + l) << 9) + (h << 6) + e] = r;
    }
}

// ---------------------------------------------------------------------------
// Softmax+AV specialized for S=96 (layer 1)
// ---------------------------------------------------------------------------
__global__ __launch_bounds__(256) void softmax_av_s96(
    const float* __restrict__ scores, const float* __restrict__ V,
    float* __restrict__ out, int Lq)
{
    __shared__ float Vs[96 * 64];
    int h = blockIdx.y, b = blockIdx.z;
    int tid = threadIdx.x, wid = tid >> 5, lane = tid & 31;
    const float* Vb = V + ((size_t)b * 96) * 512 + h * 64;
    for (int i = tid; i < 96 * 16; i += 256) {
        int s = i >> 4, c = (i & 15) * 4;
        *(float4*)&Vs[s * 64 + c] = *(const float4*)&Vb[(size_t)s * 512 + c];
    }
    __syncthreads();

    int lBase = blockIdx.x * 32 + wid * 4;
    const float* srow = scores + (((size_t)(b*HH + h) * Lq) + lBase) * 96;
#pragma unroll
    for (int rr = 0; rr < 4; rr++) {
        const float* sr = srow + rr * 96;
        float pr[3];
        pr[0] = sr[lane]; pr[1] = sr[lane + 32]; pr[2] = sr[lane + 64];
        float m = fmaxf(pr[0], fmaxf(pr[1], pr[2]));
#pragma unroll
        for (int off = 16; off > 0; off >>= 1)
            m = fmaxf(m, __shfl_xor_sync(0xffffffffu, m, off));
        pr[0] = __expf(pr[0] - m); pr[1] = __expf(pr[1] - m); pr[2] = __expf(pr[2] - m);
        float ssum = pr[0] + pr[1] + pr[2];
#pragma unroll
        for (int off = 16; off > 0; off >>= 1)
            ssum += __shfl_xor_sync(0xffffffffu, ssum, off);
        float inv = 1.f / ssum;
        float a0 = 0.f, a1 = 0.f;
#pragma unroll
        for (int j = 0; j < 3; j++)
#pragma unroll
            for (int sl = 0; sl < 32; sl++) {
                float ps = __shfl_sync(0xffffffffu, pr[j], sl);
                int s = j * 32 + sl;
                a0 = fmaf(ps, Vs[s * 64 + lane], a0);
                a1 = fmaf(ps, Vs[s * 64 + lane + 32], a1);
            }
        int l = lBase + rr;
        float* ob = out + ((size_t)(b * Lq + l)) * 512 + h * 64;
        ob[lane]      = a0 * inv;
        ob[lane + 32] = a1 * inv;
    }
}

// ---------------------------------------------------------------------------
// Trend norm
// ---------------------------------------------------------------------------
__global__ __launch_bounds__(256) void trend_norm(
    const float* __restrict__ x, const float* __restrict__ gm,
    const float* __restrict__ bt, float* __restrict__ y)
{
    __shared__ float seas[512];
    __shared__ float trend[512];
    __shared__ float red[256];
    int b = blockIdx.y, t = blockIdx.x, tid = threadIdx.x;
    const float* xb = x + (size_t)b * INDN * 512;
    float ls = 0.f, ls2 = 0.f;
    for (int d = tid; d < 512; d += 256) {
        float tr = 0.f;
#pragma unroll
        for (int j = -12; j <= 12; j++) {
            int tt = t + j;
            tt = tt < 0 ? 0 : (tt > INDN-1 ? INDN-1 : tt);
            tr += xb[(size_t)tt * 512 + d];
        }
        tr *= (1.0f / 25.0f);
        float sv = xb[(size_t)t * 512 + d] - tr;
        seas[d] = sv; trend[d] = tr;
        ls += sv; ls2 += sv * sv;
    }
    red[tid] = ls; __syncthreads();
    for (int off = 128; off > 0; off >>= 1) { if (tid < off) red[tid] += red[tid+off]; __syncthreads(); }
    float mu = red[0] * (1.f/512.f); __syncthreads();
    red[tid] = ls2; __syncthreads();
    for (int off = 128; off > 0; off >>= 1) { if (tid < off) red[tid] += red[tid+off]; __syncthreads(); }
    float var = red[0] * (1.f/512.f) - mu*mu;
    float rs = rsqrtf(var + 1e-5f);
    for (int d = tid; d < 512; d += 256)
        y[((size_t)b*INDN + t) * 512 + d] = (seas[d] - mu) * rs * gm[d] + bt[d] + trend[d];
}

// ---------------------------------------------------------------------------
// Penalties
// ---------------------------------------------------------------------------
__global__ void zero_pen() { g_pen[0] = 0.f; g_pen[1] = 0.f; }

__global__ __launch_bounds__(256) void penalty_kernel(
    const float* __restrict__ om, const float* __restrict__ th,
    int total, int seq, float scale)
{
    float omp = 0.f, thp = 0.f;
    for (int idx = blockIdx.x * 256 + threadIdx.x; idx < total; idx += gridDim.x * 256) {
        int n = idx >> 4;
        int sIn = n % seq;
        float t = th[idx]; thp += t * t;
        if (sIn < seq - 1) { float d = om[idx + 16] - om[idx]; omp += d * d; }
    }
#pragma unroll
    for (int o = 16; o > 0; o >>= 1) {
        omp += __shfl_down_sync(0xffffffffu, omp, o);
        thp += __shfl_down_sync(0xffffffffu, thp, o);
    }
    __shared__ float sho[8], sht[8];
    int wid = threadIdx.x >> 5, lid = threadIdx.x & 31;
    if (lid == 0) { sho[wid] = omp; sht[wid] = thp; }
    __syncthreads();
    if (threadIdx.x == 0) {
        float so = 0.f, st = 0.f;
        for (int w = 0; w < 8; w++) { so += sho[w]; st += sht[w]; }
        atomicAdd(&g_pen[0], so * scale);
        atomicAdd(&g_pen[1], st * scale);
    }
}

__global__ void finalize_kernel(float* out, int out_size)
{
    if (out_size >= BLD + 2) {
        out[BLD]     = g_pen[0];
        out[BLD + 1] = g_pen[1];
    }
}

// ---------------------------------------------------------------------------
// Host launcher
// ---------------------------------------------------------------------------
#define SYMADDR(p, s) do { void* _t = nullptr; cudaGetSymbolAddress(&_t, s); (p) = decltype(p)(_t); } while (0)

extern "C" void kernel_launch(void* const* d_in, const int* in_sizes, int n_in,
                              void* d_out, int out_size)
{
    (void)in_sizes; (void)n_in;
    const float* queries = (const float*)d_in[0];
    const float* keys    = (const float*)d_in[1];
    const float* values  = (const float*)d_in[2];
    const float* Wq  = (const float*)d_in[3];
    const float* bq  = (const float*)d_in[4];
    const float* Wk  = (const float*)d_in[5];
    const float* bk  = (const float*)d_in[6];
    const float* Wv  = (const float*)d_in[7];
    const float* bv  = (const float*)d_in[8];
    const float* Wqo = (const float*)d_in[9];
    const float* bqo = (const float*)d_in[10];
    const float* Wko = (const float*)d_in[11];
    const float* bko = (const float*)d_in[12];
    const float* Wqt = (const float*)d_in[13];
    const float* bqt = (const float*)d_in[14];
    const float* Wkt = (const float*)d_in[15];
    const float* bkt = (const float*)d_in[16];
    const float* Wo  = (const float*)d_in[17];
    const float* bo  = (const float*)d_in[18];
    const float* Ibuf = (const float*)d_in[19];
    const float* ln_g = (const float*)d_in[20];
    const float* ln_b = (const float*)d_in[21];
    float* out = (float*)d_out;

    const int NBS = BB * SS;      // 24576
    const int NBI = BB * INDN;    // 768
    const int W2  = 512 * 512;
    const int W2S = 512 * 16;
    const int N4  = NBS * 512 / 4;

    float *pK0, *pV0, *pQ0, *pkom0, *pkth0, *pqom0, *pqth0, *pScores;
    float *pAttn0, *pIndB, *pIndC, *pQ1, *pK1, *pV1, *pqom1, *pqth1, *pkom1, *pkth1;
    float *pAttn1;
    __nv_bfloat16 *pAhi, *pAlo, *pWThi, *pWTlo, *pQrh, *pQrl, *pKrh, *pKrl;
    SYMADDR(pK0, g_K0);     SYMADDR(pV0, g_V0);     SYMADDR(pQ0, g_Q0);
    SYMADDR(pkom0, g_kom0); SYMADDR(pkth0, g_kth0);
    SYMADDR(pqom0, g_qom0); SYMADDR(pqth0, g_qth0);
    SYMADDR(pScores, g_scores);
    SYMADDR(pAttn0, g_attn0); SYMADDR(pIndB, g_indB); SYMADDR(pIndC, g_indC);
    SYMADDR(pQ1, g_Q1);     SYMADDR(pK1, g_K1);     SYMADDR(pV1, g_V1);
    SYMADDR(pqom1, g_qom1); SYMADDR(pqth1, g_qth1);
    SYMADDR(pkom1, g_kom1); SYMADDR(pkth1, g_kth1);
    SYMADDR(pAttn1, g_attn1);
    SYMADDR(pAhi, g_ahi);   SYMADDR(pAlo, g_alo);
    SYMADDR(pWThi, g_wThi); SYMADDR(pWTlo, g_wTlo);
    SYMADDR(pQrh, g_qrh);   SYMADDR(pQrl, g_qrl);
    SYMADDR(pKrh, g_krh);   SYMADDR(pKrl, g_krl);

    dim3 gBig(4, NBS / 128);
    dim3 gWT(16, 16);

    // ------------------------ Layer 0 (inducings x keys/values) -------------
    split_f32<<<2048, 256>>>(keys, pAhi, pAlo, N4);
    split_wT<<<gWT, 256>>>(Wk, pWThi, pWTlo);
    mma_nn_bf16<<<gBig, 256>>>(pAhi, pAlo, pWThi, pWTlo, bk, pK0, NBS);

    split_f32<<<2048, 256>>>(values, pAhi, pAlo, N4);
    split_wT<<<gWT, 256>>>(Wv, pWThi, pWTlo);
    mma_nn_bf16<<<gBig, 256>>>(pAhi, pAlo, pWThi, pWTlo, bv, pV0, NBS);

    gemm_nn<<<dim3(4, 1), 256>>>(Ibuf, Wq, bq, pQ0, INDN, 512);

    gemm_omth<<<NBS/64, 256>>>(keys, Wko, bko, Wkt, bkt, pkom0, pkth0, NBS);
    gemm_omth<<<(INDN+63)/64, 256>>>(Ibuf, Wqo, bqo, Wqt, bqt, pqom0, pqth0, INDN);

    zero_pen<<<1, 1>>>();
    penalty_kernel<<<6, 256>>>(pqom0, pqth0, INDN*16, INDN, (float)BB);
    penalty_kernel<<<1024, 256>>>(pkom0, pkth0, NBS*16, SS, 1.f);

    build_qr<<<INDN, 256>>>(pQ0, pqom0, pqth0, pQrh, pQrl, INDN, 1.f/INDN);
    build_kr<<<NBS,  256>>>(pK0, pkom0, pkth0, pKrh, pKrl, SS,   1.f/SS);

    mma_nt_bf16<<<dim3(SS/128, 1, BB*HH), 256>>>(pQrh, pQrl, (size_t)0,
                                                 pKrh, pKrl, pScores, INDN, SS);
    softmax_av<<<dim3(INDN, HH, BB), 256>>>(pScores, pV0, pAttn0, INDN, SS);

    gemm_nn<<<dim3(4, 6), 256>>>(pAttn0, Wo, bo, pIndB, NBI, 512);
    trend_norm<<<dim3(INDN, BB), 256>>>(pIndB, ln_g, ln_b, pIndC);

    // ------------------------ Layer 1 (queries x inducings) -----------------
    split_f32<<<2048, 256>>>(queries, pAhi, pAlo, N4);
    split_wT<<<gWT, 256>>>(Wq + W2, pWThi, pWTlo);
    mma_nn_bf16<<<gBig, 256>>>(pAhi, pAlo, pWThi, pWTlo, bq + 512, pQ1, NBS);

    gemm_nn<<<dim3(4, 6), 256>>>(pIndC, Wk + W2, bk + 512, pK1, NBI, 512);
    gemm_nn<<<dim3(4, 6), 256>>>(pIndC, Wv + W2, bv + 512, pV1, NBI, 512);

    gemm_omth<<<NBS/64, 256>>>(queries, Wqo + W2S, bqo + 16, Wqt + W2S, bqt + 16,
                               pqom1, pqth1, NBS);
    gemm_omth<<<NBI/64, 256>>>(pIndC, Wko + W2S, bko + 16, Wkt + W2S, bkt + 16,
                               pkom1, pkth1, NBI);

    penalty_kernel<<<1024, 256>>>(pqom1, pqth1, NBS*16, LL, 1.f);
    penalty_kernel<<<48, 256>>>(pkom1, pkth1, NBI*16, INDN, 1.f);

    build_qr<<<NBS, 256>>>(pQ1, pqom1, pqth1, pQrh, pQrl, LL,   1.f/LL);
    build_kr<<<NBI, 256>>>(pK1, pkom1, pkth1, pKrh, pKrl, INDN, 1.f/INDN);

    mma_nt_bf16<<<dim3(1, LL/128, BB*HH), 256>>>(pQrh, pQrl, (size_t)LL*HH*128,
                                                 pKrh, pKrl, pScores, LL, INDN);
    softmax_av_s96<<<dim3(LL/32, HH, BB), 256>>>(pScores, pV1, pAttn1, LL);

    split_f32<<<2048, 256>>>(pAttn1, pAhi, pAlo, N4);
    split_wT<<<gWT, 256>>>(Wo + W2, pWThi, pWTlo);
    mma_nn_bf16<<<gBig, 256>>>(pAhi, pAlo, pWThi, pWTlo, bo + 512, out, NBS);

    finalize_kernel<<<1, 1>>>(out, out_size);
}

// round 9
// speedup vs baseline: 2.3464x; 1.2974x over previous
#include <cuda_runtime.h>
#include <cuda_bf16.h>
#include <math.h>
#include <stdint.h>

// Problem constants
#define BB   8
#define LL   3072
#define SS   3072
#define DD   512
#define HH   8
#define INDN 96
#define BLD  (BB*LL*DD)   // 12582912
#define PI_F 3.14159265358979323846f

typedef unsigned long long ull;

// ---------------------------------------------------------------------------
// Scratch (device globals; allocation-free per harness rules)
// ---------------------------------------------------------------------------
__device__ float g_K0   [(size_t)BB*SS*DD];
__device__ float g_V0   [(size_t)BB*SS*DD];
__device__ float g_Q0   [(size_t)INDN*DD];
__device__ float g_kom0 [(size_t)BB*SS*16];
__device__ float g_kth0 [(size_t)BB*SS*16];
__device__ float g_qom0 [(size_t)INDN*16];
__device__ float g_qth0 [(size_t)INDN*16];
__device__ float g_scores[(size_t)BB*HH*INDN*SS];  // 75.5MB, reused by layer 1
__device__ float g_attn0[(size_t)BB*INDN*DD];
__device__ float g_indB [(size_t)BB*INDN*DD];
__device__ float g_indC [(size_t)BB*INDN*DD];
__device__ float g_Q1   [(size_t)BB*LL*DD];
__device__ float g_K1   [(size_t)BB*INDN*DD];
__device__ float g_V1   [(size_t)BB*INDN*DD];
__device__ float g_qom1 [(size_t)BB*LL*16];
__device__ float g_qth1 [(size_t)BB*LL*16];
__device__ float g_kom1 [(size_t)BB*INDN*16];
__device__ float g_kth1 [(size_t)BB*INDN*16];
__device__ float g_attn1[(size_t)BB*LL*DD];
__device__ float g_pen[2];
__device__ float g_statM[(size_t)BB*HH*INDN];
__device__ float g_statI[(size_t)BB*HH*INDN];
// bf16 split buffers
__device__ __nv_bfloat16 g_ahi [(size_t)BB*SS*DD];
__device__ __nv_bfloat16 g_alo [(size_t)BB*SS*DD];
__device__ __nv_bfloat16 g_wThi[(size_t)DD*DD];
__device__ __nv_bfloat16 g_wTlo[(size_t)DD*DD];
__device__ __nv_bfloat16 g_qrh [(size_t)BB*LL*HH*128];
__device__ __nv_bfloat16 g_qrl [(size_t)BB*LL*HH*128];
__device__ __nv_bfloat16 g_krh [(size_t)BB*SS*HH*128];
__device__ __nv_bfloat16 g_krl [(size_t)BB*SS*HH*128];

// ---------------------------------------------------------------------------
// Packed f32x2 helpers
// ---------------------------------------------------------------------------
__device__ __forceinline__ ull pk2(float x, float y) {
    ull r;
    asm("mov.b64 %0, {%1, %2};" : "=l"(r) : "f"(x), "f"(y));
    return r;
}
__device__ __forceinline__ void fma2(ull& d, ull a, ull b) {
    asm("fma.rn.f32x2 %0, %1, %2, %0;" : "+l"(d) : "l"(a), "l"(b));
}
__device__ __forceinline__ float2 upk2(ull v) {
    float2 r;
    asm("mov.b64 {%0, %1}, %2;" : "=f"(r.x), "=f"(r.y) : "l"(v));
    return r;
}

// ---------------------------------------------------------------------------
// cp.async helpers (sm_80 baseline PTX)
// ---------------------------------------------------------------------------
__device__ __forceinline__ void cpa16(uint32_t dst, const void* src) {
    asm volatile("cp.async.cg.shared.global [%0], [%1], 16;"
                 :: "r"(dst), "l"(src) : "memory");
}
__device__ __forceinline__ void cpa16z(uint32_t dst, const void* src, bool v) {
    int sz = v ? 16 : 0;
    asm volatile("cp.async.cg.shared.global [%0], [%1], 16, %2;"
                 :: "r"(dst), "l"(src), "r"(sz) : "memory");
}
#define CPA_COMMIT asm volatile("cp.async.commit_group;" ::: "memory")
#define CPA_WAIT1  asm volatile("cp.async.wait_group 1;" ::: "memory")
#define CPA_WAIT0  asm volatile("cp.async.wait_group 0;" ::: "memory")

__device__ __forceinline__ uint32_t smem_u32(const void* p) {
    uint32_t a;
    asm("{ .reg .u64 t; cvta.to.shared.u64 t, %1; cvt.u32.u64 %0, t; }" : "=r"(a) : "l"(p));
    return a;
}

// ---------------------------------------------------------------------------
// bf16 mma helper (baseline PTX, sm_80+)
// ---------------------------------------------------------------------------
__device__ __forceinline__ void mma_bf16(float* c, const uint32_t* a, const uint32_t* b) {
    asm volatile(
        "mma.sync.aligned.m16n8k16.row.col.f32.bf16.bf16.f32 "
        "{%0,%1,%2,%3}, {%4,%5,%6,%7}, {%8,%9}, {%0,%1,%2,%3};"
        : "+f"(c[0]), "+f"(c[1]), "+f"(c[2]), "+f"(c[3])
        : "r"(a[0]), "r"(a[1]), "r"(a[2]), "r"(a[3]), "r"(b[0]), "r"(b[1]));
}

#define MMA_STAGE 40960
extern __shared__ char dynsm[];

// ---------------------------------------------------------------------------
// mma_nn_bf16: C[N,512] = (Ahi+Alo)[N,512] @ (WThi+WTlo)^T + bias
// cp.async double-buffered, 2 stages x 40KB dynamic smem.  N % 128 == 0.
// ---------------------------------------------------------------------------
__global__ __launch_bounds__(256) void mma_nn_bf16(
    const __nv_bfloat16* __restrict__ Ahi, const __nv_bfloat16* __restrict__ Alo,
    const __nv_bfloat16* __restrict__ Bhi, const __nv_bfloat16* __restrict__ Blo,
    const float* __restrict__ bias, float* __restrict__ C, int N)
{
    uint32_t sb = smem_u32(dynsm);
    int tid = threadIdx.x;
    int rowBase = blockIdx.y * 128, colBase = blockIdx.x * 128;
    int wid = tid >> 5, lane = tid & 31;
    int mBase = (wid >> 2) * 64, nBase = (wid & 3) * 32;

    float c[4][4][4];
#pragma unroll
    for (int ma = 0; ma < 4; ma++)
#pragma unroll
        for (int na = 0; na < 4; na++)
#pragma unroll
            for (int i = 0; i < 4; i++) c[ma][na][i] = 0.f;

    auto issue = [&](int ck, int p) {
        uint32_t base = sb + p * MMA_STAGE;
        int k0 = ck * 32;
#pragma unroll
        for (int j = 0; j < 2; j++) {
            int i = tid + j * 256;
            int row = i >> 2, seg = i & 3;
            uint32_t off = (uint32_t)(row * 20 + seg * 4) * 4;
            size_t ga = (size_t)(rowBase + row) * 512 + k0 + seg * 8;
            cpa16(base + off,         Ahi + ga);
            cpa16(base + 10240 + off, Alo + ga);
            size_t gb = (size_t)(colBase + row) * 512 + k0 + seg * 8;
            cpa16(base + 20480 + off, Bhi + gb);
            cpa16(base + 30720 + off, Blo + gb);
        }
        CPA_COMMIT;
    };

    issue(0, 0);
    for (int ck = 0; ck < 16; ck++) {
        int p = ck & 1;
        if (ck < 15) { issue(ck + 1, p ^ 1); CPA_WAIT1; } else { CPA_WAIT0; }
        __syncthreads();
        const uint32_t* AsH = (const uint32_t*)(dynsm + p * MMA_STAGE);
        const uint32_t* AsL = AsH + 2560;
        const uint32_t* BsH = AsH + 5120;
        const uint32_t* BsL = AsH + 7680;
#pragma unroll
        for (int kk = 0; kk < 16; kk += 8) {
            int kq = kk + (lane & 3);
            uint32_t bh[4][2], bl[4][2];
#pragma unroll
            for (int na = 0; na < 4; na++) {
                int n = nBase + na * 8 + (lane >> 2);
                bh[na][0] = BsH[n * 20 + kq];     bh[na][1] = BsH[n * 20 + kq + 4];
                bl[na][0] = BsL[n * 20 + kq];     bl[na][1] = BsL[n * 20 + kq + 4];
            }
#pragma unroll
            for (int ma = 0; ma < 4; ma++) {
                int r = mBase + ma * 16 + (lane >> 2);
                uint32_t ah[4], al[4];
                ah[0] = AsH[r * 20 + kq];       ah[1] = AsH[(r + 8) * 20 + kq];
                ah[2] = AsH[r * 20 + kq + 4];   ah[3] = AsH[(r + 8) * 20 + kq + 4];
                al[0] = AsL[r * 20 + kq];       al[1] = AsL[(r + 8) * 20 + kq];
                al[2] = AsL[r * 20 + kq + 4];   al[3] = AsL[(r + 8) * 20 + kq + 4];
#pragma unroll
                for (int na = 0; na < 4; na++) {
                    mma_bf16(c[ma][na], ah, bh[na]);
                    mma_bf16(c[ma][na], ah, bl[na]);
                    mma_bf16(c[ma][na], al, bh[na]);
                }
            }
        }
        __syncthreads();
    }

#pragma unroll
    for (int ma = 0; ma < 4; ma++) {
        int row0 = rowBase + mBase + ma * 16 + (lane >> 2);
        int row1 = row0 + 8;
#pragma unroll
        for (int na = 0; na < 4; na++) {
            int col = colBase + nBase + na * 8 + (lane & 3) * 2;
            float b0 = bias[col], b1 = bias[col + 1];
            if (row0 < N) {
                float2 o = make_float2(c[ma][na][0] + b0, c[ma][na][1] + b1);
                *(float2*)(C + (size_t)row0 * 512 + col) = o;
            }
            if (row1 < N) {
                float2 o = make_float2(c[ma][na][2] + b0, c[ma][na][3] + b1);
                *(float2*)(C + (size_t)row1 * 512 + col) = o;
            }
        }
    }
}

// ---------------------------------------------------------------------------
// mma_nt_bf16: scores[bh,l,s] = (1/16) * Qr[l,:].Kr[s,:]  per (b,h), K=128.
// cp.async double-buffered with zero-fill for OOB rows.
// ---------------------------------------------------------------------------
__global__ __launch_bounds__(256) void mma_nt_bf16(
    const __nv_bfloat16* __restrict__ Qh, const __nv_bfloat16* __restrict__ Ql,
    size_t qBstride,
    const __nv_bfloat16* __restrict__ Kh, const __nv_bfloat16* __restrict__ Kl,
    float* __restrict__ scores, int Lq, int S)
{
    uint32_t sb = smem_u32(dynsm);
    int tid = threadIdx.x;
    int bh = blockIdx.z, b = bh >> 3, h = bh & 7;
    size_t aOff = (size_t)b * qBstride + (size_t)h * 128;
    size_t bOff = ((size_t)b * S * HH + h) * 128;
    float* C = scores + (size_t)bh * Lq * S;
    int lBase = blockIdx.y * 128, sBase = blockIdx.x * 128;
    int wid = tid >> 5, lane = tid & 31;
    int mBase = (wid >> 2) * 64, nBase = (wid & 3) * 32;

    float c[4][4][4];
#pragma unroll
    for (int ma = 0; ma < 4; ma++)
#pragma unroll
        for (int na = 0; na < 4; na++)
#pragma unroll
            for (int i = 0; i < 4; i++) c[ma][na][i] = 0.f;

    auto issue = [&](int ck, int p) {
        uint32_t base = sb + p * MMA_STAGE;
        int k0 = ck * 32;
#pragma unroll
        for (int j = 0; j < 2; j++) {
            int i = tid + j * 256;
            int row = i >> 2, seg = i & 3;
            uint32_t off = (uint32_t)(row * 20 + seg * 4) * 4;
            int gl = lBase + row;
            bool va = gl < Lq;
            size_t ga = aOff + (size_t)(va ? gl : 0) * 1024 + k0 + seg * 8;
            cpa16z(base + off,         Qh + ga, va);
            cpa16z(base + 10240 + off, Ql + ga, va);
            int gs = sBase + row;
            bool vb = gs < S;
            size_t gb = bOff + (size_t)(vb ? gs : 0) * 1024 + k0 + seg * 8;
            cpa16z(base + 20480 + off, Kh + gb, vb);
            cpa16z(base + 30720 + off, Kl + gb, vb);
        }
        CPA_COMMIT;
    };

    issue(0, 0);
    for (int ck = 0; ck < 4; ck++) {
        int p = ck & 1;
        if (ck < 3) { issue(ck + 1, p ^ 1); CPA_WAIT1; } else { CPA_WAIT0; }
        __syncthreads();
        const uint32_t* AsH = (const uint32_t*)(dynsm + p * MMA_STAGE);
        const uint32_t* AsL = AsH + 2560;
        const uint32_t* BsH = AsH + 5120;
        const uint32_t* BsL = AsH + 7680;
#pragma unroll
        for (int kk = 0; kk < 16; kk += 8) {
            int kq = kk + (lane & 3);
            uint32_t bhf[4][2], blf[4][2];
#pragma unroll
            for (int na = 0; na < 4; na++) {
                int n = nBase + na * 8 + (lane >> 2);
                bhf[na][0] = BsH[n * 20 + kq];  bhf[na][1] = BsH[n * 20 + kq + 4];
                blf[na][0] = BsL[n * 20 + kq];  blf[na][1] = BsL[n * 20 + kq + 4];
            }
#pragma unroll
            for (int ma = 0; ma < 4; ma++) {
                int r = mBase + ma * 16 + (lane >> 2);
                uint32_t ah[4], al[4];
                ah[0] = AsH[r * 20 + kq];       ah[1] = AsH[(r + 8) * 20 + kq];
                ah[2] = AsH[r * 20 + kq + 4];   ah[3] = AsH[(r + 8) * 20 + kq + 4];
                al[0] = AsL[r * 20 + kq];       al[1] = AsL[(r + 8) * 20 + kq];
                al[2] = AsL[r * 20 + kq + 4];   al[3] = AsL[(r + 8) * 20 + kq + 4];
#pragma unroll
                for (int na = 0; na < 4; na++) {
                    mma_bf16(c[ma][na], ah, bhf[na]);
                    mma_bf16(c[ma][na], ah, blf[na]);
                    mma_bf16(c[ma][na], al, bhf[na]);
                }
            }
        }
        __syncthreads();
    }

#pragma unroll
    for (int ma = 0; ma < 4; ma++) {
        int l0 = lBase + mBase + ma * 16 + (lane >> 2);
        int l1 = l0 + 8;
#pragma unroll
        for (int na = 0; na < 4; na++) {
            int s = sBase + nBase + na * 8 + (lane & 3) * 2;
            if (s + 1 < S) {
                if (l0 < Lq) {
                    float2 o = make_float2(c[ma][na][0] * 0.0625f, c[ma][na][1] * 0.0625f);
                    *(float2*)(C + (size_t)l0 * S + s) = o;
                }
                if (l1 < Lq) {
                    float2 o = make_float2(c[ma][na][2] * 0.0625f, c[ma][na][3] * 0.0625f);
                    *(float2*)(C + (size_t)l1 * S + s) = o;
                }
            } else if (s < S) {
                if (l0 < Lq) C[(size_t)l0 * S + s] = c[ma][na][0] * 0.0625f;
                if (l1 < Lq) C[(size_t)l1 * S + s] = c[ma][na][2] * 0.0625f;
            }
        }
    }
}

// ---------------------------------------------------------------------------
// Split fp32 -> (hi, lo) bf16
// ---------------------------------------------------------------------------
__global__ __launch_bounds__(256) void split_f32(
    const float* __restrict__ x, __nv_bfloat16* __restrict__ hi,
    __nv_bfloat16* __restrict__ lo, int n4)
{
    for (int i = blockIdx.x * 256 + threadIdx.x; i < n4; i += gridDim.x * 256) {
        float4 v = ((const float4*)x)[i];
        __nv_bfloat16 h0 = __float2bfloat16(v.x);
        __nv_bfloat16 h1 = __float2bfloat16(v.y);
        __nv_bfloat16 h2 = __float2bfloat16(v.z);
        __nv_bfloat16 h3 = __float2bfloat16(v.w);
        __nv_bfloat162* hp = (__nv_bfloat162*)hi;
        __nv_bfloat162* lp = (__nv_bfloat162*)lo;
        hp[2*i]   = __nv_bfloat162(h0, h1);
        hp[2*i+1] = __nv_bfloat162(h2, h3);
        lp[2*i]   = __nv_bfloat162(__float2bfloat16(v.x - __bfloat162float(h0)),
                                   __float2bfloat16(v.y - __bfloat162float(h1)));
        lp[2*i+1] = __nv_bfloat162(__float2bfloat16(v.z - __bfloat162float(h2)),
                                   __float2bfloat16(v.w - __bfloat162float(h3)));
    }
}

// ---------------------------------------------------------------------------
// Split + transpose W[512,512] -> WT hi/lo
// ---------------------------------------------------------------------------
__global__ __launch_bounds__(256) void split_wT(
    const float* __restrict__ W, __nv_bfloat16* __restrict__ hiT,
    __nv_bfloat16* __restrict__ loT)
{
    __shared__ float t[32][33];
    int bn = blockIdx.x * 32;
    int bk = blockIdx.y * 32;
    int tx = threadIdx.x & 31, ty = threadIdx.x >> 5;
    for (int r = ty; r < 32; r += 8)
        t[r][tx] = W[(size_t)(bk + r) * 512 + bn + tx];
    __syncthreads();
    for (int r = ty; r < 32; r += 8) {
        float v = t[tx][r];
        __nv_bfloat16 h = __float2bfloat16(v);
        size_t o = (size_t)(bn + r) * 512 + bk + tx;
        hiT[o] = h;
        loT[o] = __float2bfloat16(v - __bfloat162float(h));
    }
}

// ---------------------------------------------------------------------------
// FFMA2 GEMM (NN) for small exact-fp32 GEMMs
// ---------------------------------------------------------------------------
__global__ __launch_bounds__(256, 2) void gemm_nn(
    const float* __restrict__ A, const float* __restrict__ W,
    const float* __restrict__ bias, float* __restrict__ C, int N, int P)
{
    __shared__ float As[16][132];
    __shared__ float Bs[16][132];
    int tid = threadIdx.x;
    int rowBase = blockIdx.y * 128;
    int colBase = blockIdx.x * 128;
    int ty = tid >> 4, tx = tid & 15;

    ull acc[4][8];
#pragma unroll
    for (int p = 0; p < 4; p++)
#pragma unroll
        for (int j = 0; j < 8; j++) acc[p][j] = 0ull;

    int aRow = tid >> 2;
    int aK   = (tid & 3) * 4;
    int bK   = tid >> 4;
    int bCol = (tid & 15) * 4;
    bool v0 = (rowBase + aRow) < N;
    bool v1 = (rowBase + aRow + 64) < N;
    const float* Ap0 = A + (size_t)(rowBase + aRow) * 512 + aK;
    const float* Ap1 = Ap0 + (size_t)64 * 512;
    const float* Wp  = W + (size_t)bK * P + colBase + bCol;

    for (int k0 = 0; k0 < 512; k0 += 16) {
        float4 a0 = v0 ? *(const float4*)(Ap0 + k0) : make_float4(0.f,0.f,0.f,0.f);
        float4 a1 = v1 ? *(const float4*)(Ap1 + k0) : make_float4(0.f,0.f,0.f,0.f);
        As[aK+0][aRow] = a0.x; As[aK+1][aRow] = a0.y;
        As[aK+2][aRow] = a0.z; As[aK+3][aRow] = a0.w;
        As[aK+0][aRow+64] = a1.x; As[aK+1][aRow+64] = a1.y;
        As[aK+2][aRow+64] = a1.z; As[aK+3][aRow+64] = a1.w;
        float4 b0 = *(const float4*)(Wp + (size_t)k0 * P);
        float4 b1 = *(const float4*)(Wp + (size_t)k0 * P + 64);
        *(float4*)&Bs[bK][bCol]      = b0;
        *(float4*)&Bs[bK][bCol + 64] = b1;
        __syncthreads();
#pragma unroll
        for (int k = 0; k < 16; k++) {
            float4 av0 = *(const float4*)&As[k][ty*4];
            float4 av1 = *(const float4*)&As[k][64 + ty*4];
            float4 bv0 = *(const float4*)&Bs[k][tx*4];
            float4 bv1 = *(const float4*)&Bs[k][64 + tx*4];
            ull ap[4];
            ap[0] = pk2(av0.x, av0.y); ap[1] = pk2(av0.z, av0.w);
            ap[2] = pk2(av1.x, av1.y); ap[3] = pk2(av1.z, av1.w);
            ull bd[8];
            bd[0] = pk2(bv0.x, bv0.x); bd[1] = pk2(bv0.y, bv0.y);
            bd[2] = pk2(bv0.z, bv0.z); bd[3] = pk2(bv0.w, bv0.w);
            bd[4] = pk2(bv1.x, bv1.x); bd[5] = pk2(bv1.y, bv1.y);
            bd[6] = pk2(bv1.z, bv1.z); bd[7] = pk2(bv1.w, bv1.w);
#pragma unroll
            for (int p = 0; p < 4; p++)
#pragma unroll
                for (int j = 0; j < 8; j++)
                    fma2(acc[p][j], ap[p], bd[j]);
        }
        __syncthreads();
    }

#pragma unroll
    for (int p = 0; p < 4; p++) {
        int row = rowBase + ((p < 2) ? (ty*4 + p*2) : (64 + ty*4 + (p-2)*2));
#pragma unroll
        for (int j = 0; j < 8; j++) {
            int col = colBase + ((j < 4) ? (tx*4 + j) : (64 + tx*4 + (j-4)));
            float2 r = upk2(acc[p][j]);
            float bb = bias[col];
            if (row < N)     C[(size_t)row * P + col]     = r.x + bb;
            if (row + 1 < N) C[(size_t)(row+1) * P + col] = r.y + bb;
        }
    }
}

// ---------------------------------------------------------------------------
// Fused omega/theta heads
// ---------------------------------------------------------------------------
__global__ __launch_bounds__(256) void gemm_omth(
    const float* __restrict__ A,
    const float* __restrict__ Wom, const float* __restrict__ bom,
    const float* __restrict__ Wth, const float* __restrict__ bth,
    float* __restrict__ Com, float* __restrict__ Cth, int N)
{
    __shared__ float As[16][68];
    __shared__ float Ws[16][34];
    int tid = threadIdx.x;
    int rowBase = blockIdx.x * 64;
    int ty = tid >> 4, tx = tid & 15;
    float acc[4][2] = {{0.f,0.f},{0.f,0.f},{0.f,0.f},{0.f,0.f}};

    int aRow = tid >> 2;
    int aK   = (tid & 3) * 4;
    int wK   = tid >> 4;
    int wC   = tid & 15;
    bool av = (rowBase + aRow) < N;
    const float* Ap = A + (size_t)(rowBase + aRow) * 512 + aK;

    for (int k0 = 0; k0 < 512; k0 += 16) {
        float4 a = av ? *(const float4*)(Ap + k0) : make_float4(0.f,0.f,0.f,0.f);
        As[aK+0][aRow] = a.x; As[aK+1][aRow] = a.y;
        As[aK+2][aRow] = a.z; As[aK+3][aRow] = a.w;
        Ws[wK][wC]      = Wom[(size_t)(k0 + wK) * 16 + wC];
        Ws[wK][16 + wC] = Wth[(size_t)(k0 + wK) * 16 + wC];
        __syncthreads();
#pragma unroll
        for (int k = 0; k < 16; k++) {
            float4 avv = *(const float4*)&As[k][ty*4];
            float w0 = Ws[k][tx], w1 = Ws[k][16 + tx];
            acc[0][0] = fmaf(avv.x, w0, acc[0][0]); acc[0][1] = fmaf(avv.x, w1, acc[0][1]);
            acc[1][0] = fmaf(avv.y, w0, acc[1][0]); acc[1][1] = fmaf(avv.y, w1, acc[1][1]);
            acc[2][0] = fmaf(avv.z, w0, acc[2][0]); acc[2][1] = fmaf(avv.z, w1, acc[2][1]);
            acc[3][0] = fmaf(avv.w, w0, acc[3][0]); acc[3][1] = fmaf(avv.w, w1, acc[3][1]);
        }
        __syncthreads();
    }
#pragma unroll
    for (int i = 0; i < 4; i++) {
        int row = rowBase + ty*4 + i;
        if (row >= N) continue;
        Com[(size_t)row * 16 + tx] = fmaxf(acc[i][0] + bom[tx], 0.f);
        Cth[(size_t)row * 16 + tx] = tanhf(acc[i][1] + bth[tx]) * PI_F;
    }
}

// ---------------------------------------------------------------------------
// Rotation builders -> bf16 hi/lo
// ---------------------------------------------------------------------------
__device__ __forceinline__ void wr_split(__nv_bfloat16* hi, __nv_bfloat16* lo,
                                         int idx, float v) {
    __nv_bfloat16 h = __float2bfloat16(v);
    hi[idx] = h;
    lo[idx] = __float2bfloat16(v - __bfloat162float(h));
}

__global__ void build_qr(const float* __restrict__ Q, const float* __restrict__ om,
                         const float* __restrict__ th,
                         __nv_bfloat16* __restrict__ Qh, __nv_bfloat16* __restrict__ Ql,
                         int seq, float invSeq)
{
    int row = blockIdx.x;
    int tid = threadIdx.x;
    int h = tid >> 5, m = (tid >> 4) & 1, i = tid & 15;
    float pos = (float)(row % seq) * invSeq;
    int oi = row * 16 + h * 2 + m;
    float ang = fmaf(om[oi], pos, th[oi]);
    float sn, cs; sincosf(ang, &sn, &cs);
    const float* q = Q + (size_t)row * 512 + h * 64;
    float q0 = q[i], q1 = q[16+i], q2 = q[32+i], q3 = q[48+i];
    int o = ((row * HH + h) * 128) + m * 64;
    wr_split(Qh, Ql, o + i,      q0*cs - q1*sn);
    wr_split(Qh, Ql, o + 16 + i, q1*cs + q0*sn);
    wr_split(Qh, Ql, o + 32 + i, q2*cs + q3*sn);
    wr_split(Qh, Ql, o + 48 + i, q3*cs - q2*sn);
}

__global__ void build_kr(const float* __restrict__ K, const float* __restrict__ om,
                         const float* __restrict__ th,
                         __nv_bfloat16* __restrict__ Kh, __nv_bfloat16* __restrict__ Kl,
                         int seq, float invSeq)
{
    int row = blockIdx.x;
    int tid = threadIdx.x;
    int h = tid >> 5, m = (tid >> 4) & 1, i = tid & 15;
    float pos = (float)(row % seq) * invSeq;
    int oi = row * 16 + h * 2 + m;
    float ang = fmaf(om[oi], pos, th[oi]);
    float sn, cs; sincosf(ang, &sn, &cs);
    const float* k = K + (size_t)row * 512 + h * 64;
    float k0 = k[i], k1 = k[16+i], k2 = k[32+i], k3 = k[48+i];
    int o = ((row * HH + h) * 128) + m * 64;
    wr_split(Kh, Kl, o + i,      k0*cs - k2*sn);
    wr_split(Kh, Kl, o + 16 + i, k1*cs - k3*sn);
    wr_split(Kh, Kl, o + 32 + i, k2*cs + k0*sn);
    wr_split(Kh, Kl, o + 48 + i, k3*cs + k1*sn);
}

// ---------------------------------------------------------------------------
// row_stats: per-row max and 1/sum(exp) for layer-0 softmax (rows = bh*INDN)
// ---------------------------------------------------------------------------
__global__ __launch_bounds__(256) void row_stats(
    const float* __restrict__ scores, float* __restrict__ M, float* __restrict__ I)
{
    int row = blockIdx.x * 8 + (threadIdx.x >> 5);
    int lane = threadIdx.x & 31;
    const float* r = scores + (size_t)row * SS;
    float m = -3.4e38f;
    for (int i = lane; i < SS; i += 32) m = fmaxf(m, r[i]);
#pragma unroll
    for (int o = 16; o; o >>= 1) m = fmaxf(m, __shfl_xor_sync(0xffffffffu, m, o));
    float s = 0.f;
    for (int i = lane; i < SS; i += 32) s += __expf(r[i] - m);
#pragma unroll
    for (int o = 16; o; o >>= 1) s += __shfl_xor_sync(0xffffffffu, s, o);
    if (lane == 0) { M[row] = m; I[row] = 1.f / s; }
}

// ---------------------------------------------------------------------------
// av48: out[b,l,h*64+e] = (1/S) * sum_s exp(score-M) * V[b,s,h*64+e]
// grid (2, HH, BB): 48 l-rows per block.  V+P tiles in smem, 3r x 4e regs.
// ---------------------------------------------------------------------------
__global__ __launch_bounds__(256) void av48(
    const float* __restrict__ scores, const float* __restrict__ V,
    const float* __restrict__ M, const float* __restrict__ I,
    float* __restrict__ out)
{
    __shared__ float Vs[64][64];
    __shared__ float Ps[48][65];
    __shared__ float Ms[48], Is[48];
    int h = blockIdx.y, b = blockIdx.z;
    int l0 = blockIdx.x * 48;
    int bh = b * HH + h;
    int tid = threadIdx.x;
    int eg = tid & 15;
    int rg = tid >> 4;
    if (tid < 48) {
        Ms[tid] = M[bh * INDN + l0 + tid];
        Is[tid] = I[bh * INDN + l0 + tid];
    }
    const float* S0 = scores + ((size_t)bh * INDN + l0) * SS;
    const float* Vb = V + ((size_t)b * SS) * 512 + h * 64;
    __syncthreads();
    ull acc[3][2] = {{0ull,0ull},{0ull,0ull},{0ull,0ull}};
    for (int s0 = 0; s0 < SS; s0 += 64) {
#pragma unroll
        for (int i = 0; i < 4; i++) {
            int s = (tid >> 4) + i * 16;
            *(float4*)&Vs[s][eg * 4] = *(const float4*)&Vb[(size_t)(s0 + s) * 512 + eg * 4];
        }
#pragma unroll
        for (int i = 0; i < 3; i++) {
            int idx = tid + i * 256;
            int r = idx >> 4, sseg = idx & 15;
            float4 v = *(const float4*)&S0[(size_t)r * SS + s0 + sseg * 4];
            float m = Ms[r];
            Ps[r][sseg*4+0] = __expf(v.x - m);
            Ps[r][sseg*4+1] = __expf(v.y - m);
            Ps[r][sseg*4+2] = __expf(v.z - m);
            Ps[r][sseg*4+3] = __expf(v.w - m);
        }
        __syncthreads();
#pragma unroll 4
        for (int s = 0; s < 64; s++) {
            float4 v = *(const float4*)&Vs[s][eg * 4];
            ull vA = pk2(v.x, v.y), vB = pk2(v.z, v.w);
#pragma unroll
            for (int j = 0; j < 3; j++) {
                float p = Ps[rg * 3 + j][s];
                ull pp = pk2(p, p);
                fma2(acc[j][0], pp, vA);
                fma2(acc[j][1], pp, vB);
            }
        }
        __syncthreads();
    }
#pragma unroll
    for (int j = 0; j < 3; j++) {
        int l = l0 + rg * 3 + j;
        float inv = Is[rg * 3 + j];
        float2 a = upk2(acc[j][0]), bq = upk2(acc[j][1]);
        float* o = out + ((size_t)b * INDN + l) * 512 + h * 64 + eg * 4;
        *(float4*)o = make_float4(a.x * inv, a.y * inv, bq.x * inv, bq.y * inv);
    }
}

// ---------------------------------------------------------------------------
// Softmax+AV specialized for S=96 (layer 1)
// ---------------------------------------------------------------------------
__global__ __launch_bounds__(256) void softmax_av_s96(
    const float* __restrict__ scores, const float* __restrict__ V,
    float* __restrict__ out, int Lq)
{
    __shared__ float Vs[96 * 64];
    int h = blockIdx.y, b = blockIdx.z;
    int tid = threadIdx.x, wid = tid >> 5, lane = tid & 31;
    const float* Vb = V + ((size_t)b * 96) * 512 + h * 64;
    for (int i = tid; i < 96 * 16; i += 256) {
        int s = i >> 4, c = (i & 15) * 4;
        *(float4*)&Vs[s * 64 + c] = *(const float4*)&Vb[(size_t)s * 512 + c];
    }
    __syncthreads();

    int lBase = blockIdx.x * 32 + wid * 4;
    const float* srow = scores + (((size_t)(b*HH + h) * Lq) + lBase) * 96;
#pragma unroll
    for (int rr = 0; rr < 4; rr++) {
        const float* sr = srow + rr * 96;
        float pr[3];
        pr[0] = sr[lane]; pr[1] = sr[lane + 32]; pr[2] = sr[lane + 64];
        float m = fmaxf(pr[0], fmaxf(pr[1], pr[2]));
#pragma unroll
        for (int off = 16; off > 0; off >>= 1)
            m = fmaxf(m, __shfl_xor_sync(0xffffffffu, m, off));
        pr[0] = __expf(pr[0] - m); pr[1] = __expf(pr[1] - m); pr[2] = __expf(pr[2] - m);
        float ssum = pr[0] + pr[1] + pr[2];
#pragma unroll
        for (int off = 16; off > 0; off >>= 1)
            ssum += __shfl_xor_sync(0xffffffffu, ssum, off);
        float inv = 1.f / ssum;
        float a0 = 0.f, a1 = 0.f;
#pragma unroll
        for (int j = 0; j < 3; j++)
#pragma unroll
            for (int sl = 0; sl < 32; sl++) {
                float ps = __shfl_sync(0xffffffffu, pr[j], sl);
                int s = j * 32 + sl;
                a0 = fmaf(ps, Vs[s * 64 + lane], a0);
                a1 = fmaf(ps, Vs[s * 64 + lane + 32], a1);
            }
        int l = lBase + rr;
        float* ob = out + ((size_t)(b * Lq + l)) * 512 + h * 64;
        ob[lane]      = a0 * inv;
        ob[lane + 32] = a1 * inv;
    }
}

// ---------------------------------------------------------------------------
// Trend norm
// ---------------------------------------------------------------------------
__global__ __launch_bounds__(256) void trend_norm(
    const float* __restrict__ x, const float* __restrict__ gm,
    const float* __restrict__ bt, float* __restrict__ y)
{
    __shared__ float seas[512];
    __shared__ float trend[512];
    __shared__ float red[256];
    int b = blockIdx.y, t = blockIdx.x, tid = threadIdx.x;
    const float* xb = x + (size_t)b * INDN * 512;
    float ls = 0.f, ls2 = 0.f;
    for (int d = tid; d < 512; d += 256) {
        float tr = 0.f;
#pragma unroll
        for (int j = -12; j <= 12; j++) {
            int tt = t + j;
            tt = tt < 0 ? 0 : (tt > INDN-1 ? INDN-1 : tt);
            tr += xb[(size_t)tt * 512 + d];
        }
        tr *= (1.0f / 25.0f);
        float sv = xb[(size_t)t * 512 + d] - tr;
        seas[d] = sv; trend[d] = tr;
        ls += sv; ls2 += sv * sv;
    }
    red[tid] = ls; __syncthreads();
    for (int off = 128; off > 0; off >>= 1) { if (tid < off) red[tid] += red[tid+off]; __syncthreads(); }
    float mu = red[0] * (1.f/512.f); __syncthreads();
    red[tid] = ls2; __syncthreads();
    for (int off = 128; off > 0; off >>= 1) { if (tid < off) red[tid] += red[tid+off]; __syncthreads(); }
    float var = red[0] * (1.f/512.f) - mu*mu;
    float rs = rsqrtf(var + 1e-5f);
    for (int d = tid; d < 512; d += 256)
        y[((size_t)b*INDN + t) * 512 + d] = (seas[d] - mu) * rs * gm[d] + bt[d] + trend[d];
}

// ---------------------------------------------------------------------------
// Penalties
// ---------------------------------------------------------------------------
__global__ void zero_pen() { g_pen[0] = 0.f; g_pen[1] = 0.f; }

__global__ __launch_bounds__(256) void penalty_kernel(
    const float* __restrict__ om, const float* __restrict__ th,
    int total, int seq, float scale)
{
    float omp = 0.f, thp = 0.f;
    for (int idx = blockIdx.x * 256 + threadIdx.x; idx < total; idx += gridDim.x * 256) {
        int n = idx >> 4;
        int sIn = n % seq;
        float t = th[idx]; thp += t * t;
        if (sIn < seq - 1) { float d = om[idx + 16] - om[idx]; omp += d * d; }
    }
#pragma unroll
    for (int o = 16; o > 0; o >>= 1) {
        omp += __shfl_down_sync(0xffffffffu, omp, o);
        thp += __shfl_down_sync(0xffffffffu, thp, o);
    }
    __shared__ float sho[8], sht[8];
    int wid = threadIdx.x >> 5, lid = threadIdx.x & 31;
    if (lid == 0) { sho[wid] = omp; sht[wid] = thp; }
    __syncthreads();
    if (threadIdx.x == 0) {
        float so = 0.f, st = 0.f;
        for (int w = 0; w < 8; w++) { so += sho[w]; st += sht[w]; }
        atomicAdd(&g_pen[0], so * scale);
        atomicAdd(&g_pen[1], st * scale);
    }
}

__global__ void finalize_kernel(float* out, int out_size)
{
    if (out_size >= BLD + 2) {
        out[BLD]     = g_pen[0];
        out[BLD + 1] = g_pen[1];
    }
}

// ---------------------------------------------------------------------------
// Host launcher
// ---------------------------------------------------------------------------
#define SYMADDR(p, s) do { void* _t = nullptr; cudaGetSymbolAddress(&_t, s); (p) = decltype(p)(_t); } while (0)

extern "C" void kernel_launch(void* const* d_in, const int* in_sizes, int n_in,
                              void* d_out, int out_size)
{
    (void)in_sizes; (void)n_in;
    const float* queries = (const float*)d_in[0];
    const float* keys    = (const float*)d_in[1];
    const float* values  = (const float*)d_in[2];
    const float* Wq  = (const float*)d_in[3];
    const float* bq  = (const float*)d_in[4];
    const float* Wk  = (const float*)d_in[5];
    const float* bk  = (const float*)d_in[6];
    const float* Wv  = (const float*)d_in[7];
    const float* bv  = (const float*)d_in[8];
    const float* Wqo = (const float*)d_in[9];
    const float* bqo = (const float*)d_in[10];
    const float* Wko = (const float*)d_in[11];
    const float* bko = (const float*)d_in[12];
    const float* Wqt = (const float*)d_in[13];
    const float* bqt = (const float*)d_in[14];
    const float* Wkt = (const float*)d_in[15];
    const float* bkt = (const float*)d_in[16];
    const float* Wo  = (const float*)d_in[17];
    const float* bo  = (const float*)d_in[18];
    const float* Ibuf = (const float*)d_in[19];
    const float* ln_g = (const float*)d_in[20];
    const float* ln_b = (const float*)d_in[21];
    float* out = (float*)d_out;

    const int NBS = BB * SS;      // 24576
    const int NBI = BB * INDN;    // 768
    const int W2  = 512 * 512;
    const int W2S = 512 * 16;
    const int N4  = NBS * 512 / 4;
    const int MMA_DSM = 2 * MMA_STAGE;  // 81920

    float *pK0, *pV0, *pQ0, *pkom0, *pkth0, *pqom0, *pqth0, *pScores;
    float *pAttn0, *pIndB, *pIndC, *pQ1, *pK1, *pV1, *pqom1, *pqth1, *pkom1, *pkth1;
    float *pAttn1, *pStatM, *pStatI;
    __nv_bfloat16 *pAhi, *pAlo, *pWThi, *pWTlo, *pQrh, *pQrl, *pKrh, *pKrl;
    SYMADDR(pK0, g_K0);     SYMADDR(pV0, g_V0);     SYMADDR(pQ0, g_Q0);
    SYMADDR(pkom0, g_kom0); SYMADDR(pkth0, g_kth0);
    SYMADDR(pqom0, g_qom0); SYMADDR(pqth0, g_qth0);
    SYMADDR(pScores, g_scores);
    SYMADDR(pAttn0, g_attn0); SYMADDR(pIndB, g_indB); SYMADDR(pIndC, g_indC);
    SYMADDR(pQ1, g_Q1);     SYMADDR(pK1, g_K1);     SYMADDR(pV1, g_V1);
    SYMADDR(pqom1, g_qom1); SYMADDR(pqth1, g_qth1);
    SYMADDR(pkom1, g_kom1); SYMADDR(pkth1, g_kth1);
    SYMADDR(pAttn1, g_attn1);
    SYMADDR(pStatM, g_statM); SYMADDR(pStatI, g_statI);
    SYMADDR(pAhi, g_ahi);   SYMADDR(pAlo, g_alo);
    SYMADDR(pWThi, g_wThi); SYMADDR(pWTlo, g_wTlo);
    SYMADDR(pQrh, g_qrh);   SYMADDR(pQrl, g_qrl);
    SYMADDR(pKrh, g_krh);   SYMADDR(pKrl, g_krl);

    cudaFuncSetAttribute(mma_nn_bf16, cudaFuncAttributeMaxDynamicSharedMemorySize, MMA_DSM);
    cudaFuncSetAttribute(mma_nt_bf16, cudaFuncAttributeMaxDynamicSharedMemorySize, MMA_DSM);

    dim3 gBig(4, NBS / 128);
    dim3 gWT(16, 16);

    // ------------------------ Layer 0 (inducings x keys/values) -------------
    split_f32<<<2048, 256>>>(keys, pAhi, pAlo, N4);
    split_wT<<<gWT, 256>>>(Wk, pWThi, pWTlo);
    mma_nn_bf16<<<gBig, 256, MMA_DSM>>>(pAhi, pAlo, pWThi, pWTlo, bk, pK0, NBS);

    split_f32<<<2048, 256>>>(values, pAhi, pAlo, N4);
    split_wT<<<gWT, 256>>>(Wv, pWThi, pWTlo);
    mma_nn_bf16<<<gBig, 256, MMA_DSM>>>(pAhi, pAlo, pWThi, pWTlo, bv, pV0, NBS);

    gemm_nn<<<dim3(4, 1), 256>>>(Ibuf, Wq, bq, pQ0, INDN, 512);

    gemm_omth<<<NBS/64, 256>>>(keys, Wko, bko, Wkt, bkt, pkom0, pkth0, NBS);
    gemm_omth<<<(INDN+63)/64, 256>>>(Ibuf, Wqo, bqo, Wqt, bqt, pqom0, pqth0, INDN);

    zero_pen<<<1, 1>>>();
    penalty_kernel<<<6, 256>>>(pqom0, pqth0, INDN*16, INDN, (float)BB);
    penalty_kernel<<<1024, 256>>>(pkom0, pkth0, NBS*16, SS, 1.f);

    build_qr<<<INDN, 256>>>(pQ0, pqom0, pqth0, pQrh, pQrl, INDN, 1.f/INDN);
    build_kr<<<NBS,  256>>>(pK0, pkom0, pkth0, pKrh, pKrl, SS,   1.f/SS);

    mma_nt_bf16<<<dim3(SS/128, 1, BB*HH), 256, MMA_DSM>>>(pQrh, pQrl, (size_t)0,
                                                          pKrh, pKrl, pScores, INDN, SS);
    row_stats<<<BB*HH*INDN/8, 256>>>(pScores, pStatM, pStatI);
    av48<<<dim3(2, HH, BB), 256>>>(pScores, pV0, pStatM, pStatI, pAttn0);

    gemm_nn<<<dim3(4, 6), 256>>>(pAttn0, Wo, bo, pIndB, NBI, 512);
    trend_norm<<<dim3(INDN, BB), 256>>>(pIndB, ln_g, ln_b, pIndC);

    // ------------------------ Layer 1 (queries x inducings) -----------------
    split_f32<<<2048, 256>>>(queries, pAhi, pAlo, N4);
    split_wT<<<gWT, 256>>>(Wq + W2, pWThi, pWTlo);
    mma_nn_bf16<<<gBig, 256, MMA_DSM>>>(pAhi, pAlo, pWThi, pWTlo, bq + 512, pQ1, NBS);

    gemm_nn<<<dim3(4, 6), 256>>>(pIndC, Wk + W2, bk + 512, pK1, NBI, 512);
    gemm_nn<<<dim3(4, 6), 256>>>(pIndC, Wv + W2, bv + 512, pV1, NBI, 512);

    gemm_omth<<<NBS/64, 256>>>(queries, Wqo + W2S, bqo + 16, Wqt + W2S, bqt + 16,
                               pqom1, pqth1, NBS);
    gemm_omth<<<NBI/64, 256>>>(pIndC, Wko + W2S, bko + 16, Wkt + W2S, bkt + 16,
                               pkom1, pkth1, NBI);

    penalty_kernel<<<1024, 256>>>(pqom1, pqth1, NBS*16, LL, 1.f);
    penalty_kernel<<<48, 256>>>(pkom1, pkth1, NBI*16, INDN, 1.f);

    build_qr<<<NBS, 256>>>(pQ1, pqom1, pqth1, pQrh, pQrl, LL,   1.f/LL);
    build_kr<<<NBI, 256>>>(pK1, pkom1, pkth1, pKrh, pKrl, INDN, 1.f/INDN);

    mma_nt_bf16<<<dim3(1, LL/128, BB*HH), 256, MMA_DSM>>>(pQrh, pQrl, (size_t)LL*HH*128,
                                                          pKrh, pKrl, pScores, LL, INDN);
    softmax_av_s96<<<dim3(LL/32, HH, BB), 256>>>(pScores, pV1, pAttn1, LL);

    split_f32<<<2048, 256>>>(pAttn1, pAhi, pAlo, N4);
    split_wT<<<gWT, 256>>>(Wo + W2, pWThi, pWTlo);
    mma_nn_bf16<<<gBig, 256, MMA_DSM>>>(pAhi, pAlo, pWThi, pWTlo, bo + 512, out, NBS);

    finalize_kernel<<<1, 1>>>(out, out_size);
}